// round 2
// baseline (speedup 1.0000x reference)
#include <cuda_runtime.h>
#include <math.h>
#include <stdint.h>

// ---------------------------------------------------------------------------
// Problem constants
// ---------------------------------------------------------------------------
#define B_    8
#define SP    128
#define ST    64
#define SV    64
#define SEQ   256            // SP+ST+SV
#define DMODEL 768
#define DLLM  4096
#define NH    32
#define HD    128
#define DFF   11008
#define NTOK  (B_*SEQ)       // 2048
#define EPS   1e-5f

// ---------------------------------------------------------------------------
// Scratch (single __device__ array; no allocations allowed)
// ---------------------------------------------------------------------------
#define SZ_TOKD ((size_t)NTOK*DLLM)          // 8,388,608
#define SZ_FF   ((size_t)NTOK*DFF)           // 22,544,384
#define OFF_H    ((size_t)0)
#define OFF_XN   (SZ_TOKD)
#define OFF_Q    (2*SZ_TOKD)
#define OFF_K    (3*SZ_TOKD)
#define OFF_V    (4*SZ_TOKD)
#define OFF_ATT  (5*SZ_TOKD)
#define OFF_G    (6*SZ_TOKD)
#define OFF_U    (OFF_G + SZ_FF)
#define OFF_COS  (OFF_U + SZ_FF)
#define OFF_SIN  (OFF_COS + (size_t)SEQ*64)
#define OFF_POOL (OFF_SIN + (size_t)SEQ*64)
#define OFF_Y1   (OFF_POOL + (size_t)B_*DLLM)
#define SCRATCH_TOTAL (OFF_Y1 + (size_t)B_*768)

__device__ float g_scratch[SCRATCH_TOTAL];

// ---------------------------------------------------------------------------
// SGEMM: C[M,N] = A[M,K] @ B[K,N]   (both row-major), fp32
// 128x128 block tile, BK=8, 256 threads, 8x8 per-thread register tile.
// flags: 1 = accumulate into C (+=), 2 = add bias[col], 4 = remap output rows
//        (row -> (row>>6)*SEQ + map_base + (row&63)) for text/vision scatter.
// Requires: M%128==0, N%128==0, K%8==0 (true for all calls here).
// ---------------------------------------------------------------------------
__global__ __launch_bounds__(256) void sgemm128(
    const float* __restrict__ A, const float* __restrict__ B,
    float* __restrict__ C, int M, int N, int K,
    int flags, const float* __restrict__ bias, int map_base)
{
    __shared__ float As[8][128];
    __shared__ float Bs[8][128];

    const int tid = threadIdx.x;
    const int bx = blockIdx.x, by = blockIdx.y;

    // A tile load mapping: each thread loads one float4 along K
    const int aRow = tid >> 1;            // 0..127
    const int aCol = (tid & 1) << 2;      // 0 or 4
    const float* Aptr = A + (size_t)(by * 128 + aRow) * K + aCol;

    // B tile load mapping
    const int bRow = tid >> 5;            // 0..7
    const int bCol = (tid & 31) << 2;     // 0..124
    const float* Bptr = B + (size_t)bRow * N + bx * 128 + bCol;

    const int ty = tid >> 4;              // 0..15
    const int tx = tid & 15;              // 0..15

    float acc[8][8];
#pragma unroll
    for (int i = 0; i < 8; i++)
#pragma unroll
        for (int j = 0; j < 8; j++) acc[i][j] = 0.f;

    for (int k0 = 0; k0 < K; k0 += 8) {
        float4 av = *reinterpret_cast<const float4*>(Aptr);
        float4 bv = *reinterpret_cast<const float4*>(Bptr);
        Aptr += 8;
        Bptr += (size_t)8 * N;

        As[aCol + 0][aRow] = av.x;
        As[aCol + 1][aRow] = av.y;
        As[aCol + 2][aRow] = av.z;
        As[aCol + 3][aRow] = av.w;
        *reinterpret_cast<float4*>(&Bs[bRow][bCol]) = bv;
        __syncthreads();

#pragma unroll
        for (int kk = 0; kk < 8; kk++) {
            float a[8], b[8];
#pragma unroll
            for (int i = 0; i < 8; i++) a[i] = As[kk][ty * 8 + i];
#pragma unroll
            for (int j = 0; j < 8; j++) b[j] = Bs[kk][tx * 8 + j];
#pragma unroll
            for (int i = 0; i < 8; i++)
#pragma unroll
                for (int j = 0; j < 8; j++) acc[i][j] += a[i] * b[j];
        }
        __syncthreads();
    }

    // Epilogue
#pragma unroll
    for (int i = 0; i < 8; i++) {
        int row = by * 128 + ty * 8 + i;
        int orow = row;
        if (flags & 4) orow = (row >> 6) * SEQ + map_base + (row & 63);
#pragma unroll
        for (int j = 0; j < 8; j++) {
            int col = bx * 128 + tx * 8 + j;
            float v = acc[i][j];
            if (flags & 2) v += bias[col];
            size_t idx = (size_t)orow * N + col;
            if (flags & 1) C[idx] += v;
            else           C[idx]  = v;
        }
    }
}

// ---------------------------------------------------------------------------
// RoPE tables (HF layout): cos/sin[s, i] for i in [0,64); cos[s,i+64]==cos[s,i]
// ---------------------------------------------------------------------------
__global__ void rope_table_kernel(float* __restrict__ cosb, float* __restrict__ sinb)
{
    int idx = blockIdx.x * blockDim.x + threadIdx.x;   // SEQ*64 = 16384
    if (idx >= SEQ * 64) return;
    int s = idx >> 6, i = idx & 63;
    double inv = exp(-((double)(2 * i) / 128.0) * log(10000.0));
    double ang = (double)s * inv;
    cosb[idx] = (float)cos(ang);
    sinb[idx] = (float)sin(ang);
}

// ---------------------------------------------------------------------------
// Prompt embedding gather: h[b*SEQ+r, :] = table[ids[b,r], :]  for r < SP
// ---------------------------------------------------------------------------
__global__ void embed_gather_kernel(const int* __restrict__ ids,
                                    const float* __restrict__ table,
                                    float* __restrict__ h)
{
    int idx = blockIdx.x * blockDim.x + threadIdx.x;   // B_*SP*DLLM
    if (idx >= B_ * SP * DLLM) return;
    int d = idx & (DLLM - 1);
    int r = (idx >> 12) & (SP - 1);
    int b = idx >> 19;
    int id = ids[b * SP + r];
    h[((size_t)(b * SEQ + r)) * DLLM + d] = table[(size_t)id * DLLM + d];
}

// ---------------------------------------------------------------------------
// RMSNorm: out[t,:] = x[t,:] * rsqrt(mean(x^2)+eps) * w[:]
// one block per token, 256 threads
// ---------------------------------------------------------------------------
__global__ __launch_bounds__(256) void rmsnorm_kernel(
    const float* __restrict__ x, const float* __restrict__ w,
    float* __restrict__ out)
{
    int t = blockIdx.x;
    const float4* xr = reinterpret_cast<const float4*>(x + (size_t)t * DLLM);
    float4 vals[4];
    float s = 0.f;
#pragma unroll
    for (int j = 0; j < 4; j++) {
        float4 v = xr[threadIdx.x + j * 256];
        vals[j] = v;
        s += v.x * v.x + v.y * v.y + v.z * v.z + v.w * v.w;
    }
#pragma unroll
    for (int off = 16; off > 0; off >>= 1) s += __shfl_xor_sync(0xffffffffu, s, off);
    __shared__ float red[8];
    __shared__ float sscale;
    if ((threadIdx.x & 31) == 0) red[threadIdx.x >> 5] = s;
    __syncthreads();
    if (threadIdx.x == 0) {
        float r = 0.f;
#pragma unroll
        for (int i = 0; i < 8; i++) r += red[i];
        sscale = rsqrtf(r * (1.0f / DLLM) + EPS);
    }
    __syncthreads();
    float sc = sscale;
    const float4* w4 = reinterpret_cast<const float4*>(w);
    float4* o4 = reinterpret_cast<float4*>(out + (size_t)t * DLLM);
#pragma unroll
    for (int j = 0; j < 4; j++) {
        float4 v = vals[j];
        float4 wv = w4[threadIdx.x + j * 256];
        o4[threadIdx.x + j * 256] =
            make_float4(v.x * sc * wv.x, v.y * sc * wv.y,
                        v.z * sc * wv.z, v.w * sc * wv.w);
    }
}

// ---------------------------------------------------------------------------
// RoPE apply in-place to q and k
// ---------------------------------------------------------------------------
__global__ void rope_apply_kernel(float* __restrict__ q, float* __restrict__ k,
                                  const float* __restrict__ cosb,
                                  const float* __restrict__ sinb)
{
    int idx = blockIdx.x * blockDim.x + threadIdx.x;   // NTOK*NH*64
    if (idx >= NTOK * NH * 64) return;
    int i = idx & 63;
    int h = (idx >> 6) & (NH - 1);
    int t = idx >> 11;
    int s = t & (SEQ - 1);
    float c = cosb[s * 64 + i];
    float sn = sinb[s * 64 + i];
    size_t base = (size_t)t * DLLM + h * HD + i;
    float x1 = q[base], x2 = q[base + 64];
    q[base]      = x1 * c - x2 * sn;
    q[base + 64] = x2 * c + x1 * sn;
    x1 = k[base]; x2 = k[base + 64];
    k[base]      = x1 * c - x2 * sn;
    k[base + 64] = x2 * c + x1 * sn;
}

// ---------------------------------------------------------------------------
// Causal attention. grid (SEQ/8, NH, B_), 256 threads = 8 warps,
// one query row per warp, scores kept in smem, online 2-pass softmax.
// ---------------------------------------------------------------------------
__global__ __launch_bounds__(256) void attention_kernel(
    const float* __restrict__ q, const float* __restrict__ k,
    const float* __restrict__ v, float* __restrict__ out)
{
    __shared__ float sc[8][SEQ];
    const int b = blockIdx.z, hh = blockIdx.y;
    const int w = threadIdx.x >> 5, lane = threadIdx.x & 31;
    const int qi = blockIdx.x * 8 + w;
    const float scale = 0.088388347648318447f;   // 1/sqrt(128)

    const float* qrow = q + (size_t)(b * SEQ + qi) * DLLM + hh * HD;
    float4 qv = reinterpret_cast<const float4*>(qrow)[lane];

    const float* kbase = k + (size_t)b * SEQ * DLLM + hh * HD;
    for (int kk = 0; kk <= qi; kk++) {
        float4 kv = reinterpret_cast<const float4*>(kbase + (size_t)kk * DLLM)[lane];
        float d = qv.x * kv.x + qv.y * kv.y + qv.z * kv.z + qv.w * kv.w;
#pragma unroll
        for (int off = 16; off > 0; off >>= 1) d += __shfl_xor_sync(0xffffffffu, d, off);
        if (lane == 0) sc[w][kk] = d * scale;
    }
    __syncwarp();

    float m = -1e30f;
    for (int kk = lane; kk <= qi; kk += 32) m = fmaxf(m, sc[w][kk]);
#pragma unroll
    for (int off = 16; off > 0; off >>= 1) m = fmaxf(m, __shfl_xor_sync(0xffffffffu, m, off));

    float ssum = 0.f;
    for (int kk = lane; kk <= qi; kk += 32) {
        float p = expf(sc[w][kk] - m);
        sc[w][kk] = p;
        ssum += p;
    }
#pragma unroll
    for (int off = 16; off > 0; off >>= 1) ssum += __shfl_xor_sync(0xffffffffu, ssum, off);
    __syncwarp();
    float inv = 1.0f / ssum;

    const float* vbase = v + (size_t)b * SEQ * DLLM + hh * HD;
    float4 acc = make_float4(0.f, 0.f, 0.f, 0.f);
    for (int kk = 0; kk <= qi; kk++) {
        float p = sc[w][kk];
        float4 vv = reinterpret_cast<const float4*>(vbase + (size_t)kk * DLLM)[lane];
        acc.x += p * vv.x; acc.y += p * vv.y;
        acc.z += p * vv.z; acc.w += p * vv.w;
    }
    float* orow = out + (size_t)(b * SEQ + qi) * DLLM + hh * HD;
    reinterpret_cast<float4*>(orow)[lane] =
        make_float4(acc.x * inv, acc.y * inv, acc.z * inv, acc.w * inv);
}

// ---------------------------------------------------------------------------
// SwiGLU: g = silu(g) * u, elementwise
// ---------------------------------------------------------------------------
__global__ void silu_mul_kernel(float* __restrict__ g, const float* __restrict__ u,
                                size_t n)
{
    size_t idx = (size_t)blockIdx.x * blockDim.x + threadIdx.x;
    if (idx >= n) return;
    float x = g[idx];
    g[idx] = (x / (1.0f + expf(-x))) * u[idx];
}

// ---------------------------------------------------------------------------
// Pool: pooled[b,d] = mean_s xn[b*SEQ+s, d]
// ---------------------------------------------------------------------------
__global__ void pool_kernel(const float* __restrict__ xn, float* __restrict__ pooled)
{
    int idx = blockIdx.x * blockDim.x + threadIdx.x;   // B_*DLLM = 32768
    if (idx >= B_ * DLLM) return;
    int b = idx >> 12, d = idx & (DLLM - 1);
    float s = 0.f;
    for (int t = 0; t < SEQ; t++)
        s += xn[(size_t)(b * SEQ + t) * DLLM + d];
    pooled[idx] = s * (1.0f / SEQ);
}

// ---------------------------------------------------------------------------
// Head: y1[b,j] = pooled[b,:] @ out1_W[:,j] + out1_b[j]
// ---------------------------------------------------------------------------
__global__ void head1_kernel(const float* __restrict__ pooled,
                             const float* __restrict__ W,
                             const float* __restrict__ bias,
                             float* __restrict__ y1)
{
    int b = blockIdx.x, j = threadIdx.x;   // blockDim = 768
    const float* p = pooled + (size_t)b * DLLM;
    float s = bias[j];
    for (int i = 0; i < DLLM; i++) s += p[i] * W[(size_t)i * 768 + j];
    y1[b * 768 + j] = s;
}

__global__ void head2_kernel(const float* __restrict__ y1,
                             const float* __restrict__ W,
                             const float* __restrict__ bias,
                             float* __restrict__ out)
{
    int b = blockIdx.x;
    float s = 0.f;
    for (int j = threadIdx.x; j < 768; j += 256) s += y1[b * 768 + j] * W[j];
#pragma unroll
    for (int off = 16; off > 0; off >>= 1) s += __shfl_xor_sync(0xffffffffu, s, off);
    __shared__ float red[8];
    if ((threadIdx.x & 31) == 0) red[threadIdx.x >> 5] = s;
    __syncthreads();
    if (threadIdx.x == 0) {
        float r = 0.f;
#pragma unroll
        for (int i = 0; i < 8; i++) r += red[i];
        out[b] = r + bias[0];
    }
}

// ---------------------------------------------------------------------------
// Launcher
// ---------------------------------------------------------------------------
extern "C" void kernel_launch(void* const* d_in, const int* in_sizes, int n_in,
                              void* d_out, int out_size)
{
    const float* text  = (const float*)d_in[0];   // [8,64,768]
    const float* vis   = (const float*)d_in[1];   // [8,64,768]
    const int*   ids   = (const int*)  d_in[2];   // [8,128]
    const float* inW   = (const float*)d_in[3];   // [768,4096]
    const float* inb   = (const float*)d_in[4];   // [4096]
    const float* etab  = (const float*)d_in[5];   // [32000,4096]
    const float* Wq    = (const float*)d_in[6];   // [2,4096,4096]
    const float* Wk    = (const float*)d_in[7];
    const float* Wv    = (const float*)d_in[8];
    const float* Wo    = (const float*)d_in[9];
    const float* ln1   = (const float*)d_in[10];  // [2,4096]
    const float* ln2   = (const float*)d_in[11];
    const float* Wg    = (const float*)d_in[12];  // [2,4096,11008]
    const float* Wu    = (const float*)d_in[13];
    const float* Wd    = (const float*)d_in[14];  // [2,11008,4096]
    const float* fnw   = (const float*)d_in[15];  // [4096]
    const float* o1W   = (const float*)d_in[16];  // [4096,768]
    const float* o1b   = (const float*)d_in[17];
    const float* o2W   = (const float*)d_in[18];  // [768,1]
    const float* o2b   = (const float*)d_in[19];
    float* out = (float*)d_out;

    float* S = nullptr;
    cudaGetSymbolAddress((void**)&S, g_scratch);
    float* h    = S + OFF_H;
    float* xn   = S + OFF_XN;
    float* q    = S + OFF_Q;
    float* k    = S + OFF_K;
    float* v    = S + OFF_V;
    float* att  = S + OFF_ATT;
    float* gbuf = S + OFF_G;
    float* ubuf = S + OFF_U;
    float* cosb = S + OFF_COS;
    float* sinb = S + OFF_SIN;
    float* pooled = S + OFF_POOL;
    float* y1   = S + OFF_Y1;

    // RoPE tables
    rope_table_kernel<<<(SEQ * 64 + 255) / 256, 256>>>(cosb, sinb);

    // Build h = concat([embed(prompt), text@inW+b, vision@inW+b], axis=1)
    embed_gather_kernel<<<(B_ * SP * DLLM + 255) / 256, 256>>>(ids, etab, h);
    sgemm128<<<dim3(DLLM / 128, (B_ * ST) / 128), 256>>>(
        text, inW, h, B_ * ST, DLLM, DMODEL, 2 | 4, inb, SP);
    sgemm128<<<dim3(DLLM / 128, (B_ * SV) / 128), 256>>>(
        vis, inW, h, B_ * SV, DLLM, DMODEL, 2 | 4, inb, SP + ST);

    const size_t wq_stride = (size_t)DLLM * DLLM;        // 16,777,216
    const size_t wf_stride = (size_t)DLLM * DFF;         // 45,088,768

    for (int l = 0; l < 2; l++) {
        // --- Attention block ---
        rmsnorm_kernel<<<NTOK, 256>>>(h, ln1 + (size_t)l * DLLM, xn);
        sgemm128<<<dim3(DLLM / 128, NTOK / 128), 256>>>(
            xn, Wq + l * wq_stride, q, NTOK, DLLM, DLLM, 0, nullptr, 0);
        sgemm128<<<dim3(DLLM / 128, NTOK / 128), 256>>>(
            xn, Wk + l * wq_stride, k, NTOK, DLLM, DLLM, 0, nullptr, 0);
        sgemm128<<<dim3(DLLM / 128, NTOK / 128), 256>>>(
            xn, Wv + l * wq_stride, v, NTOK, DLLM, DLLM, 0, nullptr, 0);
        rope_apply_kernel<<<(NTOK * NH * 64 + 255) / 256, 256>>>(q, k, cosb, sinb);
        attention_kernel<<<dim3(SEQ / 8, NH, B_), 256>>>(q, k, v, att);
        sgemm128<<<dim3(DLLM / 128, NTOK / 128), 256>>>(
            att, Wo + l * wq_stride, h, NTOK, DLLM, DLLM, 1, nullptr, 0);

        // --- MLP block ---
        rmsnorm_kernel<<<NTOK, 256>>>(h, ln2 + (size_t)l * DLLM, xn);
        sgemm128<<<dim3(DFF / 128, NTOK / 128), 256>>>(
            xn, Wg + l * wf_stride, gbuf, NTOK, DFF, DLLM, 0, nullptr, 0);
        sgemm128<<<dim3(DFF / 128, NTOK / 128), 256>>>(
            xn, Wu + l * wf_stride, ubuf, NTOK, DFF, DLLM, 0, nullptr, 0);
        silu_mul_kernel<<<(int)((SZ_FF + 255) / 256), 256>>>(gbuf, ubuf, SZ_FF);
        sgemm128<<<dim3(DLLM / 128, NTOK / 128), 256>>>(
            gbuf, Wd + l * wf_stride, h, NTOK, DLLM, DFF, 1, nullptr, 0);
    }

    // Final norm, pool, head
    rmsnorm_kernel<<<NTOK, 256>>>(h, fnw, xn);
    pool_kernel<<<(B_ * DLLM + 255) / 256, 256>>>(xn, pooled);
    head1_kernel<<<B_, 768>>>(pooled, o1W, o1b, y1);
    head2_kernel<<<B_, 256>>>(y1, o2W, o2b, out);
}

// round 4
// speedup vs baseline: 1.0005x; 1.0005x over previous
#include <cuda_runtime.h>
#include <math.h>
#include <stdint.h>

// ---------------------------------------------------------------------------
// Problem constants
// ---------------------------------------------------------------------------
#define B_    8
#define SP    128
#define ST    64
#define SV    64
#define SEQ   256            // SP+ST+SV
#define DMODEL 768
#define DLLM  4096
#define NH    32
#define HD    128
#define DFF   11008
#define NTOK  (B_*SEQ)       // 2048
#define EPS   1e-5f

// ---------------------------------------------------------------------------
// Scratch (single __device__ array; no allocations allowed)
// ---------------------------------------------------------------------------
#define SZ_TOKD ((size_t)NTOK*DLLM)          // 8,388,608
#define SZ_FF   ((size_t)NTOK*DFF)           // 22,544,384
#define OFF_H    ((size_t)0)
#define OFF_XN   (SZ_TOKD)
#define OFF_Q    (2*SZ_TOKD)
#define OFF_K    (3*SZ_TOKD)
#define OFF_V    (4*SZ_TOKD)
#define OFF_ATT  (5*SZ_TOKD)
#define OFF_G    (6*SZ_TOKD)
#define OFF_U    (OFF_G + SZ_FF)
#define OFF_COS  (OFF_U + SZ_FF)
#define OFF_SIN  (OFF_COS + (size_t)SEQ*64)
#define OFF_POOL (OFF_SIN + (size_t)SEQ*64)
#define OFF_Y1   (OFF_POOL + (size_t)B_*DLLM)
#define SCRATCH_TOTAL (OFF_Y1 + (size_t)B_*768)

__device__ float g_scratch[SCRATCH_TOTAL];

// ---------------------------------------------------------------------------
// SGEMM: C[M,N] = A[M,K] @ B[K,N]   (both row-major), fp32
// 128x128 block tile, BK=8, 256 threads, 8x8 per-thread register tile.
// flags: 1 = accumulate into C (+=), 2 = add bias[col], 4 = remap output rows
//        (row -> (row>>6)*SEQ + map_base + (row&63)) for text/vision scatter.
// Requires: M%128==0, N%128==0, K%8==0 (true for all calls here).
// ---------------------------------------------------------------------------
__global__ __launch_bounds__(256) void sgemm128(
    const float* __restrict__ A, const float* __restrict__ B,
    float* __restrict__ C, int M, int N, int K,
    int flags, const float* __restrict__ bias, int map_base)
{
    __shared__ float As[8][128];
    __shared__ float Bs[8][128];

    const int tid = threadIdx.x;
    const int bx = blockIdx.x, by = blockIdx.y;

    // A tile load mapping: each thread loads one float4 along K
    const int aRow = tid >> 1;            // 0..127
    const int aCol = (tid & 1) << 2;      // 0 or 4
    const float* Aptr = A + (size_t)(by * 128 + aRow) * K + aCol;

    // B tile load mapping
    const int bRow = tid >> 5;            // 0..7
    const int bCol = (tid & 31) << 2;     // 0..124
    const float* Bptr = B + (size_t)bRow * N + bx * 128 + bCol;

    const int ty = tid >> 4;              // 0..15
    const int tx = tid & 15;              // 0..15

    float acc[8][8];
#pragma unroll
    for (int i = 0; i < 8; i++)
#pragma unroll
        for (int j = 0; j < 8; j++) acc[i][j] = 0.f;

    for (int k0 = 0; k0 < K; k0 += 8) {
        float4 av = *reinterpret_cast<const float4*>(Aptr);
        float4 bv = *reinterpret_cast<const float4*>(Bptr);
        Aptr += 8;
        Bptr += (size_t)8 * N;

        As[aCol + 0][aRow] = av.x;
        As[aCol + 1][aRow] = av.y;
        As[aCol + 2][aRow] = av.z;
        As[aCol + 3][aRow] = av.w;
        *reinterpret_cast<float4*>(&Bs[bRow][bCol]) = bv;
        __syncthreads();

#pragma unroll
        for (int kk = 0; kk < 8; kk++) {
            float a[8], b[8];
#pragma unroll
            for (int i = 0; i < 8; i++) a[i] = As[kk][ty * 8 + i];
#pragma unroll
            for (int j = 0; j < 8; j++) b[j] = Bs[kk][tx * 8 + j];
#pragma unroll
            for (int i = 0; i < 8; i++)
#pragma unroll
                for (int j = 0; j < 8; j++) acc[i][j] += a[i] * b[j];
        }
        __syncthreads();
    }

    // Epilogue
#pragma unroll
    for (int i = 0; i < 8; i++) {
        int row = by * 128 + ty * 8 + i;
        int orow = row;
        if (flags & 4) orow = (row >> 6) * SEQ + map_base + (row & 63);
#pragma unroll
        for (int j = 0; j < 8; j++) {
            int col = bx * 128 + tx * 8 + j;
            float v = acc[i][j];
            if (flags & 2) v += bias[col];
            size_t idx = (size_t)orow * N + col;
            if (flags & 1) C[idx] += v;
            else           C[idx]  = v;
        }
    }
}

// ---------------------------------------------------------------------------
// RoPE tables (HF layout): cos/sin[s, i] for i in [0,64); cos[s,i+64]==cos[s,i]
// ---------------------------------------------------------------------------
__global__ void rope_table_kernel(float* __restrict__ cosb, float* __restrict__ sinb)
{
    int idx = blockIdx.x * blockDim.x + threadIdx.x;   // SEQ*64 = 16384
    if (idx >= SEQ * 64) return;
    int s = idx >> 6, i = idx & 63;
    double inv = exp(-((double)(2 * i) / 128.0) * log(10000.0));
    double ang = (double)s * inv;
    cosb[idx] = (float)cos(ang);
    sinb[idx] = (float)sin(ang);
}

// ---------------------------------------------------------------------------
// Prompt embedding gather: h[b*SEQ+r, :] = table[ids[b,r], :]  for r < SP
// ---------------------------------------------------------------------------
__global__ void embed_gather_kernel(const int* __restrict__ ids,
                                    const float* __restrict__ table,
                                    float* __restrict__ h)
{
    int idx = blockIdx.x * blockDim.x + threadIdx.x;   // B_*SP*DLLM
    if (idx >= B_ * SP * DLLM) return;
    int d = idx & (DLLM - 1);
    int r = (idx >> 12) & (SP - 1);
    int b = idx >> 19;
    int id = ids[b * SP + r];
    h[((size_t)(b * SEQ + r)) * DLLM + d] = table[(size_t)id * DLLM + d];
}

// ---------------------------------------------------------------------------
// RMSNorm: out[t,:] = x[t,:] * rsqrt(mean(x^2)+eps) * w[:]
// one block per token, 256 threads
// ---------------------------------------------------------------------------
__global__ __launch_bounds__(256) void rmsnorm_kernel(
    const float* __restrict__ x, const float* __restrict__ w,
    float* __restrict__ out)
{
    int t = blockIdx.x;
    const float4* xr = reinterpret_cast<const float4*>(x + (size_t)t * DLLM);
    float4 vals[4];
    float s = 0.f;
#pragma unroll
    for (int j = 0; j < 4; j++) {
        float4 v = xr[threadIdx.x + j * 256];
        vals[j] = v;
        s += v.x * v.x + v.y * v.y + v.z * v.z + v.w * v.w;
    }
#pragma unroll
    for (int off = 16; off > 0; off >>= 1) s += __shfl_xor_sync(0xffffffffu, s, off);
    __shared__ float red[8];
    __shared__ float sscale;
    if ((threadIdx.x & 31) == 0) red[threadIdx.x >> 5] = s;
    __syncthreads();
    if (threadIdx.x == 0) {
        float r = 0.f;
#pragma unroll
        for (int i = 0; i < 8; i++) r += red[i];
        sscale = rsqrtf(r * (1.0f / DLLM) + EPS);
    }
    __syncthreads();
    float sc = sscale;
    const float4* w4 = reinterpret_cast<const float4*>(w);
    float4* o4 = reinterpret_cast<float4*>(out + (size_t)t * DLLM);
#pragma unroll
    for (int j = 0; j < 4; j++) {
        float4 v = vals[j];
        float4 wv = w4[threadIdx.x + j * 256];
        o4[threadIdx.x + j * 256] =
            make_float4(v.x * sc * wv.x, v.y * sc * wv.y,
                        v.z * sc * wv.z, v.w * sc * wv.w);
    }
}

// ---------------------------------------------------------------------------
// RoPE apply in-place to q and k
// ---------------------------------------------------------------------------
__global__ void rope_apply_kernel(float* __restrict__ q, float* __restrict__ k,
                                  const float* __restrict__ cosb,
                                  const float* __restrict__ sinb)
{
    int idx = blockIdx.x * blockDim.x + threadIdx.x;   // NTOK*NH*64
    if (idx >= NTOK * NH * 64) return;
    int i = idx & 63;
    int h = (idx >> 6) & (NH - 1);
    int t = idx >> 11;
    int s = t & (SEQ - 1);
    float c = cosb[s * 64 + i];
    float sn = sinb[s * 64 + i];
    size_t base = (size_t)t * DLLM + h * HD + i;
    float x1 = q[base], x2 = q[base + 64];
    q[base]      = x1 * c - x2 * sn;
    q[base + 64] = x2 * c + x1 * sn;
    x1 = k[base]; x2 = k[base + 64];
    k[base]      = x1 * c - x2 * sn;
    k[base + 64] = x2 * c + x1 * sn;
}

// ---------------------------------------------------------------------------
// Causal attention. grid (SEQ/8, NH, B_), 256 threads = 8 warps,
// one query row per warp, scores kept in smem, online 2-pass softmax.
// ---------------------------------------------------------------------------
__global__ __launch_bounds__(256) void attention_kernel(
    const float* __restrict__ q, const float* __restrict__ k,
    const float* __restrict__ v, float* __restrict__ out)
{
    __shared__ float sc[8][SEQ];
    const int b = blockIdx.z, hh = blockIdx.y;
    const int w = threadIdx.x >> 5, lane = threadIdx.x & 31;
    const int qi = blockIdx.x * 8 + w;
    const float scale = 0.088388347648318447f;   // 1/sqrt(128)

    const float* qrow = q + (size_t)(b * SEQ + qi) * DLLM + hh * HD;
    float4 qv = reinterpret_cast<const float4*>(qrow)[lane];

    const float* kbase = k + (size_t)b * SEQ * DLLM + hh * HD;
    for (int kk = 0; kk <= qi; kk++) {
        float4 kv = reinterpret_cast<const float4*>(kbase + (size_t)kk * DLLM)[lane];
        float d = qv.x * kv.x + qv.y * kv.y + qv.z * kv.z + qv.w * kv.w;
#pragma unroll
        for (int off = 16; off > 0; off >>= 1) d += __shfl_xor_sync(0xffffffffu, d, off);
        if (lane == 0) sc[w][kk] = d * scale;
    }
    __syncwarp();

    float m = -1e30f;
    for (int kk = lane; kk <= qi; kk += 32) m = fmaxf(m, sc[w][kk]);
#pragma unroll
    for (int off = 16; off > 0; off >>= 1) m = fmaxf(m, __shfl_xor_sync(0xffffffffu, m, off));

    float ssum = 0.f;
    for (int kk = lane; kk <= qi; kk += 32) {
        float p = expf(sc[w][kk] - m);
        sc[w][kk] = p;
        ssum += p;
    }
#pragma unroll
    for (int off = 16; off > 0; off >>= 1) ssum += __shfl_xor_sync(0xffffffffu, ssum, off);
    __syncwarp();
    float inv = 1.0f / ssum;

    const float* vbase = v + (size_t)b * SEQ * DLLM + hh * HD;
    float4 acc = make_float4(0.f, 0.f, 0.f, 0.f);
    for (int kk = 0; kk <= qi; kk++) {
        float p = sc[w][kk];
        float4 vv = reinterpret_cast<const float4*>(vbase + (size_t)kk * DLLM)[lane];
        acc.x += p * vv.x; acc.y += p * vv.y;
        acc.z += p * vv.z; acc.w += p * vv.w;
    }
    float* orow = out + (size_t)(b * SEQ + qi) * DLLM + hh * HD;
    reinterpret_cast<float4*>(orow)[lane] =
        make_float4(acc.x * inv, acc.y * inv, acc.z * inv, acc.w * inv);
}

// ---------------------------------------------------------------------------
// SwiGLU: g = silu(g) * u, elementwise
// ---------------------------------------------------------------------------
__global__ void silu_mul_kernel(float* __restrict__ g, const float* __restrict__ u,
                                size_t n)
{
    size_t idx = (size_t)blockIdx.x * blockDim.x + threadIdx.x;
    if (idx >= n) return;
    float x = g[idx];
    g[idx] = (x / (1.0f + expf(-x))) * u[idx];
}

// ---------------------------------------------------------------------------
// Pool: pooled[b,d] = mean_s xn[b*SEQ+s, d]
// ---------------------------------------------------------------------------
__global__ void pool_kernel(const float* __restrict__ xn, float* __restrict__ pooled)
{
    int idx = blockIdx.x * blockDim.x + threadIdx.x;   // B_*DLLM = 32768
    if (idx >= B_ * DLLM) return;
    int b = idx >> 12, d = idx & (DLLM - 1);
    float s = 0.f;
    for (int t = 0; t < SEQ; t++)
        s += xn[(size_t)(b * SEQ + t) * DLLM + d];
    pooled[idx] = s * (1.0f / SEQ);
}

// ---------------------------------------------------------------------------
// Head: y1[b,j] = pooled[b,:] @ out1_W[:,j] + out1_b[j]
// ---------------------------------------------------------------------------
__global__ void head1_kernel(const float* __restrict__ pooled,
                             const float* __restrict__ W,
                             const float* __restrict__ bias,
                             float* __restrict__ y1)
{
    int b = blockIdx.x, j = threadIdx.x;   // blockDim = 768
    const float* p = pooled + (size_t)b * DLLM;
    float s = bias[j];
    for (int i = 0; i < DLLM; i++) s += p[i] * W[(size_t)i * 768 + j];
    y1[b * 768 + j] = s;
}

__global__ void head2_kernel(const float* __restrict__ y1,
                             const float* __restrict__ W,
                             const float* __restrict__ bias,
                             float* __restrict__ out)
{
    int b = blockIdx.x;
    float s = 0.f;
    for (int j = threadIdx.x; j < 768; j += 256) s += y1[b * 768 + j] * W[j];
#pragma unroll
    for (int off = 16; off > 0; off >>= 1) s += __shfl_xor_sync(0xffffffffu, s, off);
    __shared__ float red[8];
    if ((threadIdx.x & 31) == 0) red[threadIdx.x >> 5] = s;
    __syncthreads();
    if (threadIdx.x == 0) {
        float r = 0.f;
#pragma unroll
        for (int i = 0; i < 8; i++) r += red[i];
        out[b] = r + bias[0];
    }
}

// ---------------------------------------------------------------------------
// Launcher
// ---------------------------------------------------------------------------
extern "C" void kernel_launch(void* const* d_in, const int* in_sizes, int n_in,
                              void* d_out, int out_size)
{
    const float* text  = (const float*)d_in[0];   // [8,64,768]
    const float* vis   = (const float*)d_in[1];   // [8,64,768]
    const int*   ids   = (const int*)  d_in[2];   // [8,128]
    const float* inW   = (const float*)d_in[3];   // [768,4096]
    const float* inb   = (const float*)d_in[4];   // [4096]
    const float* etab  = (const float*)d_in[5];   // [32000,4096]
    const float* Wq    = (const float*)d_in[6];   // [2,4096,4096]
    const float* Wk    = (const float*)d_in[7];
    const float* Wv    = (const float*)d_in[8];
    const float* Wo    = (const float*)d_in[9];
    const float* ln1   = (const float*)d_in[10];  // [2,4096]
    const float* ln2   = (const float*)d_in[11];
    const float* Wg    = (const float*)d_in[12];  // [2,4096,11008]
    const float* Wu    = (const float*)d_in[13];
    const float* Wd    = (const float*)d_in[14];  // [2,11008,4096]
    const float* fnw   = (const float*)d_in[15];  // [4096]
    const float* o1W   = (const float*)d_in[16];  // [4096,768]
    const float* o1b   = (const float*)d_in[17];
    const float* o2W   = (const float*)d_in[18];  // [768,1]
    const float* o2b   = (const float*)d_in[19];
    float* out = (float*)d_out;

    float* S = nullptr;
    cudaGetSymbolAddress((void**)&S, g_scratch);
    float* h    = S + OFF_H;
    float* xn   = S + OFF_XN;
    float* q    = S + OFF_Q;
    float* k    = S + OFF_K;
    float* v    = S + OFF_V;
    float* att  = S + OFF_ATT;
    float* gbuf = S + OFF_G;
    float* ubuf = S + OFF_U;
    float* cosb = S + OFF_COS;
    float* sinb = S + OFF_SIN;
    float* pooled = S + OFF_POOL;
    float* y1   = S + OFF_Y1;

    // RoPE tables
    rope_table_kernel<<<(SEQ * 64 + 255) / 256, 256>>>(cosb, sinb);

    // Build h = concat([embed(prompt), text@inW+b, vision@inW+b], axis=1)
    embed_gather_kernel<<<(B_ * SP * DLLM + 255) / 256, 256>>>(ids, etab, h);
    sgemm128<<<dim3(DLLM / 128, (B_ * ST) / 128), 256>>>(
        text, inW, h, B_ * ST, DLLM, DMODEL, 2 | 4, inb, SP);
    sgemm128<<<dim3(DLLM / 128, (B_ * SV) / 128), 256>>>(
        vis, inW, h, B_ * SV, DLLM, DMODEL, 2 | 4, inb, SP + ST);

    const size_t wq_stride = (size_t)DLLM * DLLM;        // 16,777,216
    const size_t wf_stride = (size_t)DLLM * DFF;         // 45,088,768

    for (int l = 0; l < 2; l++) {
        // --- Attention block ---
        rmsnorm_kernel<<<NTOK, 256>>>(h, ln1 + (size_t)l * DLLM, xn);
        sgemm128<<<dim3(DLLM / 128, NTOK / 128), 256>>>(
            xn, Wq + l * wq_stride, q, NTOK, DLLM, DLLM, 0, nullptr, 0);
        sgemm128<<<dim3(DLLM / 128, NTOK / 128), 256>>>(
            xn, Wk + l * wq_stride, k, NTOK, DLLM, DLLM, 0, nullptr, 0);
        sgemm128<<<dim3(DLLM / 128, NTOK / 128), 256>>>(
            xn, Wv + l * wq_stride, v, NTOK, DLLM, DLLM, 0, nullptr, 0);
        rope_apply_kernel<<<(NTOK * NH * 64 + 255) / 256, 256>>>(q, k, cosb, sinb);
        attention_kernel<<<dim3(SEQ / 8, NH, B_), 256>>>(q, k, v, att);
        sgemm128<<<dim3(DLLM / 128, NTOK / 128), 256>>>(
            att, Wo + l * wq_stride, h, NTOK, DLLM, DLLM, 1, nullptr, 0);

        // --- MLP block ---
        rmsnorm_kernel<<<NTOK, 256>>>(h, ln2 + (size_t)l * DLLM, xn);
        sgemm128<<<dim3(DFF / 128, NTOK / 128), 256>>>(
            xn, Wg + l * wf_stride, gbuf, NTOK, DFF, DLLM, 0, nullptr, 0);
        sgemm128<<<dim3(DFF / 128, NTOK / 128), 256>>>(
            xn, Wu + l * wf_stride, ubuf, NTOK, DFF, DLLM, 0, nullptr, 0);
        silu_mul_kernel<<<(int)((SZ_FF + 255) / 256), 256>>>(gbuf, ubuf, SZ_FF);
        sgemm128<<<dim3(DLLM / 128, NTOK / 128), 256>>>(
            gbuf, Wd + l * wf_stride, h, NTOK, DLLM, DFF, 1, nullptr, 0);
    }

    // Final norm, pool, head
    rmsnorm_kernel<<<NTOK, 256>>>(h, fnw, xn);
    pool_kernel<<<(B_ * DLLM + 255) / 256, 256>>>(xn, pooled);
    head1_kernel<<<B_, 768>>>(pooled, o1W, o1b, y1);
    head2_kernel<<<B_, 256>>>(y1, o2W, o2b, out);
}

// round 7
// speedup vs baseline: 2.2665x; 2.2654x over previous
#include <cuda_runtime.h>
#include <cuda_bf16.h>
#include <math.h>
#include <stdint.h>

#define B_    8
#define SP    128
#define ST    64
#define SV    64
#define SEQ   256
#define DMODEL 768
#define DLLM  4096
#define NH    32
#define HD    128
#define DFF   11008
#define NTOK  (B_*SEQ)
#define EPS   1e-5f

// ---------------- fp32 scratch ----------------
#define SZ_TOKD ((size_t)NTOK*DLLM)
#define SZ_FF   ((size_t)NTOK*DFF)
#define OFF_H    ((size_t)0)
#define OFF_XN   (SZ_TOKD)
#define OFF_Q    (2*SZ_TOKD)
#define OFF_K    (3*SZ_TOKD)
#define OFF_V    (4*SZ_TOKD)
#define OFF_ATT  (5*SZ_TOKD)
#define OFF_G    (6*SZ_TOKD)
#define OFF_U    (OFF_G + SZ_FF)
#define OFF_COS  (OFF_U + SZ_FF)
#define OFF_SIN  (OFF_COS + (size_t)SEQ*64)
#define OFF_POOL (OFF_SIN + (size_t)SEQ*64)
#define OFF_Y1   (OFF_POOL + (size_t)B_*DLLM)
#define SCRATCH_TOTAL (OFF_Y1 + (size_t)B_*768)
__device__ float g_scratch[SCRATCH_TOTAL];

// ---------------- bf16 scratch ----------------
#define W4 ((size_t)DLLM*DLLM)
#define WF ((size_t)DLLM*DFF)
#define SZ_TV  ((size_t)512*DMODEL)
#define SZ_INW ((size_t)DMODEL*DLLM)
#define BO_XNH  ((size_t)0)
#define BO_XNL  (BO_XNH + SZ_TOKD)
#define BO_ATH  (BO_XNL + SZ_TOKD)
#define BO_ATL  (BO_ATH + SZ_TOKD)
#define BO_GH   (BO_ATL + SZ_TOKD)
#define BO_GL   (BO_GH + SZ_FF)
#define BO_TXH  (BO_GL + SZ_FF)
#define BO_TXL  (BO_TXH + SZ_TV)
#define BO_VXH  (BO_TXL + SZ_TV)
#define BO_VXL  (BO_VXH + SZ_TV)
#define BO_INWH (BO_VXL + SZ_TV)
#define BO_INWL (BO_INWH + SZ_INW)
#define BO_QH   (BO_INWL + SZ_INW)
#define BO_QL   (BO_QH + 2*W4)
#define BO_KH   (BO_QL + 2*W4)
#define BO_KL   (BO_KH + 2*W4)
#define BO_VH   (BO_KL + 2*W4)
#define BO_VL   (BO_VH + 2*W4)
#define BO_OH   (BO_VL + 2*W4)
#define BO_OL   (BO_OH + 2*W4)
#define BO_GWH  (BO_OL + 2*W4)
#define BO_GWL  (BO_GWH + 2*WF)
#define BO_UWH  (BO_GWL + 2*WF)
#define BO_UWL  (BO_UWH + 2*WF)
#define BO_DWH  (BO_UWL + 2*WF)
#define BO_DWL  (BO_DWH + 2*WF)
#define BF_TOTAL (BO_DWL + 2*WF)
__device__ __align__(256) __nv_bfloat16 g_bf[BF_TOTAL];

// ---------------- helpers ----------------
__device__ __forceinline__ uint32_t smem_u32(const void* p) {
    uint32_t a;
    asm("{ .reg .u64 t; cvta.to.shared.u64 t, %1; cvt.u32.u64 %0, t; }" : "=r"(a) : "l"(p));
    return a;
}
__device__ __forceinline__ void cp16(uint32_t d, const void* s) {
    asm volatile("cp.async.cg.shared.global [%0], [%1], 16;" :: "r"(d), "l"(s));
}
__device__ __forceinline__ void split_bf(float x, __nv_bfloat16& h, __nv_bfloat16& l) {
    h = __float2bfloat16_rn(x);
    l = __float2bfloat16_rn(x - __bfloat162float(h));
}
__device__ __forceinline__ void mma_bf16(float* c,
    uint32_t a0, uint32_t a1, uint32_t a2, uint32_t a3, uint32_t b0, uint32_t b1) {
    asm volatile(
        "mma.sync.aligned.m16n8k16.row.col.f32.bf16.bf16.f32 "
        "{%0,%1,%2,%3}, {%4,%5,%6,%7}, {%8,%9}, {%0,%1,%2,%3};"
        : "+f"(c[0]), "+f"(c[1]), "+f"(c[2]), "+f"(c[3])
        : "r"(a0), "r"(a1), "r"(a2), "r"(a3), "r"(b0), "r"(b1));
}

// ---------------------------------------------------------------------------
// mma.sync bf16-split GEMM: C[M,N] = A[M,K] @ W[K,N]
// A = Ah+Al [M,K] bf16; W^T = Bh+Bl [N,K] bf16 (K contiguous).
// 3 passes AhBh + AhBl + AlBh, fp32 accum. BM=BN=128, BK=32, 3-stage cp.async.
// smem tile pitch = 40 bf16 (conflict-free fragment loads).
// flags: 1 accumulate, 2 bias, 4 row remap. M%128==0, N%128==0, K%32==0.
// ---------------------------------------------------------------------------
#define TPITCH 40
#define TILE_E (128*TPITCH)          // 5120 elements per tile
#define STAGE_E (4*TILE_E)           // 20480 elements (Ah,Al,Bh,Bl)
#define GSMEM_BYTES (3*STAGE_E*2)    // 122880 B

__global__ __launch_bounds__(256, 1) void gemm_tc(
    const __nv_bfloat16* __restrict__ Ah, const __nv_bfloat16* __restrict__ Al,
    const __nv_bfloat16* __restrict__ Bh, const __nv_bfloat16* __restrict__ Bl,
    float* __restrict__ C, int M, int N, int K,
    int flags, const float* __restrict__ bias, int map_base)
{
    extern __shared__ __nv_bfloat16 sm[];
    const int tid = threadIdx.x;
    const int wid = tid >> 5, lane = tid & 31;
    const int wm = wid & 3, wn = wid >> 2;        // 4 m-warps x 2 n-warps
    const int m0 = blockIdx.y * 128, n0 = blockIdx.x * 128;
    const int gr = lane >> 2, qc = lane & 3;

    // Loader: 2048 16B chunks / stage, 8 per thread.
    const __nv_bfloat16* gp[8];
    uint32_t soff[8];
#pragma unroll
    for (int i = 0; i < 8; i++) {
        int c = tid + i * 256;
        int tile = c >> 9, local = c & 511, row = local >> 2, sub = local & 3;
        const __nv_bfloat16* base = (tile == 0) ? Ah : (tile == 1) ? Al
                                  : (tile == 2) ? Bh : Bl;
        int grow = ((tile < 2) ? m0 : n0) + row;
        gp[i] = base + (size_t)grow * K + sub * 8;
        soff[i] = tile * TILE_E + row * TPITCH + sub * 8;
    }

#define LOAD_STAGE(s_) do { \
    __nv_bfloat16* sb_ = sm + ((s_) % 3) * STAGE_E; \
    _Pragma("unroll") \
    for (int i_ = 0; i_ < 8; i_++) \
        cp16(smem_u32(sb_ + soff[i_]), gp[i_] + (size_t)(s_) * 32); \
    asm volatile("cp.async.commit_group;" ::: "memory"); \
} while (0)

    const int S = K / 32;
    LOAD_STAGE(0);
    LOAD_STAGE(1);

    float acc[2][8][4];
#pragma unroll
    for (int t = 0; t < 2; t++)
#pragma unroll
        for (int n = 0; n < 8; n++)
#pragma unroll
            for (int e = 0; e < 4; e++) acc[t][n][e] = 0.f;

    for (int s = 0; s < S; s++) {
        asm volatile("cp.async.wait_group 1;" ::: "memory");
        __syncthreads();
        if (s + 2 < S) { LOAD_STAGE(s + 2); }
        else { asm volatile("cp.async.commit_group;" ::: "memory"); }

        const __nv_bfloat16* sb  = sm + (s % 3) * STAGE_E;
        const __nv_bfloat16* tAh = sb;
        const __nv_bfloat16* tAl = sb + TILE_E;
        const __nv_bfloat16* tBh = sb + 2 * TILE_E;
        const __nv_bfloat16* tBl = sb + 3 * TILE_E;

#pragma unroll
        for (int kk = 0; kk < 32; kk += 16) {
            uint32_t ah[2][4], al[2][4], bh[8][2], bl[8][2];
#pragma unroll
            for (int t = 0; t < 2; t++) {
                const __nv_bfloat16* p = tAh + (wm * 32 + t * 16 + gr) * TPITCH + kk + qc * 2;
                ah[t][0] = *(const uint32_t*)p;
                ah[t][1] = *(const uint32_t*)(p + 8 * TPITCH);
                ah[t][2] = *(const uint32_t*)(p + 8);
                ah[t][3] = *(const uint32_t*)(p + 8 * TPITCH + 8);
                const __nv_bfloat16* p2 = tAl + (wm * 32 + t * 16 + gr) * TPITCH + kk + qc * 2;
                al[t][0] = *(const uint32_t*)p2;
                al[t][1] = *(const uint32_t*)(p2 + 8 * TPITCH);
                al[t][2] = *(const uint32_t*)(p2 + 8);
                al[t][3] = *(const uint32_t*)(p2 + 8 * TPITCH + 8);
            }
#pragma unroll
            for (int n = 0; n < 8; n++) {
                const __nv_bfloat16* p = tBh + (wn * 64 + n * 8 + gr) * TPITCH + kk + qc * 2;
                bh[n][0] = *(const uint32_t*)p;
                bh[n][1] = *(const uint32_t*)(p + 8);
                const __nv_bfloat16* p2 = tBl + (wn * 64 + n * 8 + gr) * TPITCH + kk + qc * 2;
                bl[n][0] = *(const uint32_t*)p2;
                bl[n][1] = *(const uint32_t*)(p2 + 8);
            }
#pragma unroll
            for (int t = 0; t < 2; t++)
#pragma unroll
                for (int n = 0; n < 8; n++) {
                    mma_bf16(acc[t][n], ah[t][0], ah[t][1], ah[t][2], ah[t][3],
                             bh[n][0], bh[n][1]);
                    mma_bf16(acc[t][n], ah[t][0], ah[t][1], ah[t][2], ah[t][3],
                             bl[n][0], bl[n][1]);
                    mma_bf16(acc[t][n], al[t][0], al[t][1], al[t][2], al[t][3],
                             bh[n][0], bh[n][1]);
                }
        }
    }

    // Epilogue
#pragma unroll
    for (int t = 0; t < 2; t++) {
#pragma unroll
        for (int half = 0; half < 2; half++) {
            int grow = m0 + wm * 32 + t * 16 + gr + half * 8;
            int orow = (flags & 4) ? ((grow >> 6) * SEQ + map_base + (grow & 63)) : grow;
            float* crow = C + (size_t)orow * N;
#pragma unroll
            for (int n = 0; n < 8; n++) {
                int col = n0 + wn * 64 + n * 8 + qc * 2;
                float2 v;
                v.x = acc[t][n][half * 2 + 0];
                v.y = acc[t][n][half * 2 + 1];
                if (flags & 2) {
                    float2 b2 = *reinterpret_cast<const float2*>(bias + col);
                    v.x += b2.x; v.y += b2.y;
                }
                if (flags & 1) {
                    float2 o = *reinterpret_cast<const float2*>(crow + col);
                    v.x += o.x; v.y += o.y;
                }
                *reinterpret_cast<float2*>(crow + col) = v;
            }
        }
    }
#undef LOAD_STAGE
}

// ---------------- transpose + split: src[K,N] fp32 -> [N,K] bf16 hi/lo ------
__global__ void transpose_split_kernel(
    const float* __restrict__ src,
    __nv_bfloat16* __restrict__ dhi, __nv_bfloat16* __restrict__ dlo,
    int K, int N)
{
    __shared__ float tile[32][33];
    const int n0 = blockIdx.x * 32, k0 = blockIdx.y * 32;
    const int tx = threadIdx.x, ty = threadIdx.y;   // 32 x 8
#pragma unroll
    for (int i = 0; i < 32; i += 8)
        tile[ty + i][tx] = src[(size_t)(k0 + ty + i) * N + n0 + tx];
    __syncthreads();
#pragma unroll
    for (int i = 0; i < 32; i += 8) {
        float v = tile[tx][ty + i];
        __nv_bfloat16 h, l;
        split_bf(v, h, l);
        size_t idx = (size_t)(n0 + ty + i) * K + k0 + tx;
        dhi[idx] = h; dlo[idx] = l;
    }
}

__global__ void split_kernel(const float* __restrict__ src,
                             __nv_bfloat16* __restrict__ hi,
                             __nv_bfloat16* __restrict__ lo, size_t n)
{
    size_t idx = (size_t)blockIdx.x * blockDim.x + threadIdx.x;
    if (idx >= n) return;
    __nv_bfloat16 h, l;
    split_bf(src[idx], h, l);
    hi[idx] = h; lo[idx] = l;
}

__global__ void rope_table_kernel(float* __restrict__ cosb, float* __restrict__ sinb)
{
    int idx = blockIdx.x * blockDim.x + threadIdx.x;
    if (idx >= SEQ * 64) return;
    int s = idx >> 6, i = idx & 63;
    double inv = exp(-((double)(2 * i) / 128.0) * log(10000.0));
    double ang = (double)s * inv;
    cosb[idx] = (float)cos(ang);
    sinb[idx] = (float)sin(ang);
}

__global__ void embed_gather_kernel(const int* __restrict__ ids,
                                    const float* __restrict__ table,
                                    float* __restrict__ h)
{
    int idx = blockIdx.x * blockDim.x + threadIdx.x;
    if (idx >= B_ * SP * DLLM) return;
    int d = idx & (DLLM - 1);
    int r = (idx >> 12) & (SP - 1);
    int b = idx >> 19;
    int id = ids[b * SP + r];
    h[((size_t)(b * SEQ + r)) * DLLM + d] = table[(size_t)id * DLLM + d];
}

__global__ __launch_bounds__(256) void rmsnorm_kernel(
    const float* __restrict__ x, const float* __restrict__ w, float* __restrict__ out)
{
    int t = blockIdx.x;
    const float4* xr = reinterpret_cast<const float4*>(x + (size_t)t * DLLM);
    float4 vals[4];
    float s = 0.f;
#pragma unroll
    for (int j = 0; j < 4; j++) {
        float4 v = xr[threadIdx.x + j * 256];
        vals[j] = v;
        s += v.x * v.x + v.y * v.y + v.z * v.z + v.w * v.w;
    }
#pragma unroll
    for (int off = 16; off > 0; off >>= 1) s += __shfl_xor_sync(0xffffffffu, s, off);
    __shared__ float red[8];
    __shared__ float sscale;
    if ((threadIdx.x & 31) == 0) red[threadIdx.x >> 5] = s;
    __syncthreads();
    if (threadIdx.x == 0) {
        float r = 0.f;
#pragma unroll
        for (int i = 0; i < 8; i++) r += red[i];
        sscale = rsqrtf(r * (1.0f / DLLM) + EPS);
    }
    __syncthreads();
    float sc = sscale;
    const float4* w4 = reinterpret_cast<const float4*>(w);
    float4* o4 = reinterpret_cast<float4*>(out + (size_t)t * DLLM);
#pragma unroll
    for (int j = 0; j < 4; j++) {
        float4 v = vals[j];
        float4 wv = w4[threadIdx.x + j * 256];
        o4[threadIdx.x + j * 256] = make_float4(
            v.x * sc * wv.x, v.y * sc * wv.y, v.z * sc * wv.z, v.w * sc * wv.w);
    }
}

__global__ __launch_bounds__(256) void rmsnorm_split_kernel(
    const float* __restrict__ x, const float* __restrict__ w,
    __nv_bfloat16* __restrict__ ohi, __nv_bfloat16* __restrict__ olo)
{
    int t = blockIdx.x;
    const float4* xr = reinterpret_cast<const float4*>(x + (size_t)t * DLLM);
    float4 vals[4];
    float s = 0.f;
#pragma unroll
    for (int j = 0; j < 4; j++) {
        float4 v = xr[threadIdx.x + j * 256];
        vals[j] = v;
        s += v.x * v.x + v.y * v.y + v.z * v.z + v.w * v.w;
    }
#pragma unroll
    for (int off = 16; off > 0; off >>= 1) s += __shfl_xor_sync(0xffffffffu, s, off);
    __shared__ float red[8];
    __shared__ float sscale;
    if ((threadIdx.x & 31) == 0) red[threadIdx.x >> 5] = s;
    __syncthreads();
    if (threadIdx.x == 0) {
        float r = 0.f;
#pragma unroll
        for (int i = 0; i < 8; i++) r += red[i];
        sscale = rsqrtf(r * (1.0f / DLLM) + EPS);
    }
    __syncthreads();
    float sc = sscale;
    const float4* w4 = reinterpret_cast<const float4*>(w);
    size_t base = (size_t)t * DLLM;
#pragma unroll
    for (int j = 0; j < 4; j++) {
        float4 v = vals[j];
        float4 wv = w4[threadIdx.x + j * 256];
        float rr[4] = { v.x * sc * wv.x, v.y * sc * wv.y, v.z * sc * wv.z, v.w * sc * wv.w };
        size_t o = base + ((size_t)threadIdx.x + j * 256) * 4;
#pragma unroll
        for (int e = 0; e < 4; e++) {
            __nv_bfloat16 h, l;
            split_bf(rr[e], h, l);
            ohi[o + e] = h; olo[o + e] = l;
        }
    }
}

__global__ void rope_apply_kernel(float* __restrict__ q, float* __restrict__ k,
                                  const float* __restrict__ cosb,
                                  const float* __restrict__ sinb)
{
    int idx = blockIdx.x * blockDim.x + threadIdx.x;
    if (idx >= NTOK * NH * 64) return;
    int i = idx & 63;
    int h = (idx >> 6) & (NH - 1);
    int t = idx >> 11;
    int s = t & (SEQ - 1);
    float c = cosb[s * 64 + i];
    float sn = sinb[s * 64 + i];
    size_t base = (size_t)t * DLLM + h * HD + i;
    float x1 = q[base], x2 = q[base + 64];
    q[base]      = x1 * c - x2 * sn;
    q[base + 64] = x2 * c + x1 * sn;
    x1 = k[base]; x2 = k[base + 64];
    k[base]      = x1 * c - x2 * sn;
    k[base + 64] = x2 * c + x1 * sn;
}

__global__ __launch_bounds__(256) void attention_kernel(
    const float* __restrict__ q, const float* __restrict__ k,
    const float* __restrict__ v, float* __restrict__ out)
{
    __shared__ float sc[8][SEQ];
    const int b = blockIdx.z, hh = blockIdx.y;
    const int w = threadIdx.x >> 5, lane = threadIdx.x & 31;
    const int qi = blockIdx.x * 8 + w;
    const float scale = 0.088388347648318447f;

    const float* qrow = q + (size_t)(b * SEQ + qi) * DLLM + hh * HD;
    float4 qv = reinterpret_cast<const float4*>(qrow)[lane];

    const float* kbase = k + (size_t)b * SEQ * DLLM + hh * HD;
    for (int kk = 0; kk <= qi; kk++) {
        float4 kv = reinterpret_cast<const float4*>(kbase + (size_t)kk * DLLM)[lane];
        float d = qv.x * kv.x + qv.y * kv.y + qv.z * kv.z + qv.w * kv.w;
#pragma unroll
        for (int off = 16; off > 0; off >>= 1) d += __shfl_xor_sync(0xffffffffu, d, off);
        if (lane == 0) sc[w][kk] = d * scale;
    }
    __syncwarp();

    float m = -1e30f;
    for (int kk = lane; kk <= qi; kk += 32) m = fmaxf(m, sc[w][kk]);
#pragma unroll
    for (int off = 16; off > 0; off >>= 1) m = fmaxf(m, __shfl_xor_sync(0xffffffffu, m, off));

    float ssum = 0.f;
    for (int kk = lane; kk <= qi; kk += 32) {
        float p = expf(sc[w][kk] - m);
        sc[w][kk] = p;
        ssum += p;
    }
#pragma unroll
    for (int off = 16; off > 0; off >>= 1) ssum += __shfl_xor_sync(0xffffffffu, ssum, off);
    __syncwarp();
    float inv = 1.0f / ssum;

    const float* vbase = v + (size_t)b * SEQ * DLLM + hh * HD;
    float4 acc = make_float4(0.f, 0.f, 0.f, 0.f);
    for (int kk = 0; kk <= qi; kk++) {
        float p = sc[w][kk];
        float4 vv = reinterpret_cast<const float4*>(vbase + (size_t)kk * DLLM)[lane];
        acc.x += p * vv.x; acc.y += p * vv.y;
        acc.z += p * vv.z; acc.w += p * vv.w;
    }
    float* orow = out + (size_t)(b * SEQ + qi) * DLLM + hh * HD;
    reinterpret_cast<float4*>(orow)[lane] =
        make_float4(acc.x * inv, acc.y * inv, acc.z * inv, acc.w * inv);
}

__global__ void silu_mul_split_kernel(const float* __restrict__ g,
                                      const float* __restrict__ u,
                                      __nv_bfloat16* __restrict__ ohi,
                                      __nv_bfloat16* __restrict__ olo, size_t n)
{
    size_t idx = (size_t)blockIdx.x * blockDim.x + threadIdx.x;
    if (idx >= n) return;
    float x = g[idx];
    float r = (x / (1.0f + expf(-x))) * u[idx];
    __nv_bfloat16 h, l;
    split_bf(r, h, l);
    ohi[idx] = h; olo[idx] = l;
}

__global__ void pool_kernel(const float* __restrict__ xn, float* __restrict__ pooled)
{
    int idx = blockIdx.x * blockDim.x + threadIdx.x;
    if (idx >= B_ * DLLM) return;
    int b = idx >> 12, d = idx & (DLLM - 1);
    float s = 0.f;
    for (int t = 0; t < SEQ; t++)
        s += xn[(size_t)(b * SEQ + t) * DLLM + d];
    pooled[idx] = s * (1.0f / SEQ);
}

__global__ void head1_kernel(const float* __restrict__ pooled,
                             const float* __restrict__ W,
                             const float* __restrict__ bias,
                             float* __restrict__ y1)
{
    int b = blockIdx.x, j = threadIdx.x;
    const float* p = pooled + (size_t)b * DLLM;
    float s = bias[j];
    for (int i = 0; i < DLLM; i++) s += p[i] * W[(size_t)i * 768 + j];
    y1[b * 768 + j] = s;
}

__global__ void head2_kernel(const float* __restrict__ y1,
                             const float* __restrict__ W,
                             const float* __restrict__ bias,
                             float* __restrict__ out)
{
    int b = blockIdx.x;
    float s = 0.f;
    for (int j = threadIdx.x; j < 768; j += 256) s += y1[b * 768 + j] * W[j];
#pragma unroll
    for (int off = 16; off > 0; off >>= 1) s += __shfl_xor_sync(0xffffffffu, s, off);
    __shared__ float red[8];
    if ((threadIdx.x & 31) == 0) red[threadIdx.x >> 5] = s;
    __syncthreads();
    if (threadIdx.x == 0) {
        float r = 0.f;
#pragma unroll
        for (int i = 0; i < 8; i++) r += red[i];
        out[b] = r + bias[0];
    }
}

// ---------------------------------------------------------------------------
extern "C" void kernel_launch(void* const* d_in, const int* in_sizes, int n_in,
                              void* d_out, int out_size)
{
    const float* text  = (const float*)d_in[0];
    const float* vis   = (const float*)d_in[1];
    const int*   ids   = (const int*)  d_in[2];
    const float* inW   = (const float*)d_in[3];
    const float* inb   = (const float*)d_in[4];
    const float* etab  = (const float*)d_in[5];
    const float* Wq    = (const float*)d_in[6];
    const float* Wk    = (const float*)d_in[7];
    const float* Wv    = (const float*)d_in[8];
    const float* Wo    = (const float*)d_in[9];
    const float* ln1   = (const float*)d_in[10];
    const float* ln2   = (const float*)d_in[11];
    const float* Wg    = (const float*)d_in[12];
    const float* Wu    = (const float*)d_in[13];
    const float* Wd    = (const float*)d_in[14];
    const float* fnw   = (const float*)d_in[15];
    const float* o1W   = (const float*)d_in[16];
    const float* o1b   = (const float*)d_in[17];
    const float* o2W   = (const float*)d_in[18];
    const float* o2b   = (const float*)d_in[19];
    float* out = (float*)d_out;

    cudaFuncSetAttribute(gemm_tc, cudaFuncAttributeMaxDynamicSharedMemorySize,
                         GSMEM_BYTES);

    float* S = nullptr;
    cudaGetSymbolAddress((void**)&S, g_scratch);
    __nv_bfloat16* BS = nullptr;
    cudaGetSymbolAddress((void**)&BS, g_bf);

    float* h    = S + OFF_H;
    float* xn   = S + OFF_XN;
    float* q    = S + OFF_Q;
    float* k    = S + OFF_K;
    float* v    = S + OFF_V;
    float* att  = S + OFF_ATT;
    float* gbuf = S + OFF_G;
    float* ubuf = S + OFF_U;
    float* cosb = S + OFF_COS;
    float* sinb = S + OFF_SIN;
    float* pooled = S + OFF_POOL;
    float* y1   = S + OFF_Y1;

    __nv_bfloat16 *xnh = BS + BO_XNH, *xnl = BS + BO_XNL;
    __nv_bfloat16 *ath = BS + BO_ATH, *atl = BS + BO_ATL;
    __nv_bfloat16 *gh  = BS + BO_GH,  *gl  = BS + BO_GL;
    __nv_bfloat16 *txh = BS + BO_TXH, *txl = BS + BO_TXL;
    __nv_bfloat16 *vxh = BS + BO_VXH, *vxl = BS + BO_VXL;
    __nv_bfloat16 *inwh = BS + BO_INWH, *inwl = BS + BO_INWL;

    dim3 t32(32, 8);

    rope_table_kernel<<<(SEQ * 64 + 255) / 256, 256>>>(cosb, sinb);

    transpose_split_kernel<<<dim3(DLLM / 32, DMODEL / 32), t32>>>(inW, inwh, inwl, DMODEL, DLLM);
    for (int l = 0; l < 2; l++) {
        transpose_split_kernel<<<dim3(DLLM / 32, DLLM / 32), t32>>>(
            Wq + (size_t)l * W4, BS + BO_QH + (size_t)l * W4, BS + BO_QL + (size_t)l * W4, DLLM, DLLM);
        transpose_split_kernel<<<dim3(DLLM / 32, DLLM / 32), t32>>>(
            Wk + (size_t)l * W4, BS + BO_KH + (size_t)l * W4, BS + BO_KL + (size_t)l * W4, DLLM, DLLM);
        transpose_split_kernel<<<dim3(DLLM / 32, DLLM / 32), t32>>>(
            Wv + (size_t)l * W4, BS + BO_VH + (size_t)l * W4, BS + BO_VL + (size_t)l * W4, DLLM, DLLM);
        transpose_split_kernel<<<dim3(DLLM / 32, DLLM / 32), t32>>>(
            Wo + (size_t)l * W4, BS + BO_OH + (size_t)l * W4, BS + BO_OL + (size_t)l * W4, DLLM, DLLM);
        transpose_split_kernel<<<dim3(DFF / 32, DLLM / 32), t32>>>(
            Wg + (size_t)l * WF, BS + BO_GWH + (size_t)l * WF, BS + BO_GWL + (size_t)l * WF, DLLM, DFF);
        transpose_split_kernel<<<dim3(DFF / 32, DLLM / 32), t32>>>(
            Wu + (size_t)l * WF, BS + BO_UWH + (size_t)l * WF, BS + BO_UWL + (size_t)l * WF, DLLM, DFF);
        transpose_split_kernel<<<dim3(DLLM / 32, DFF / 32), t32>>>(
            Wd + (size_t)l * WF, BS + BO_DWH + (size_t)l * WF, BS + BO_DWL + (size_t)l * WF, DFF, DLLM);
    }

    embed_gather_kernel<<<(B_ * SP * DLLM + 255) / 256, 256>>>(ids, etab, h);
    split_kernel<<<(int)((SZ_TV + 255) / 256), 256>>>(text, txh, txl, SZ_TV);
    split_kernel<<<(int)((SZ_TV + 255) / 256), 256>>>(vis, vxh, vxl, SZ_TV);
    gemm_tc<<<dim3(DLLM / 128, 512 / 128), 256, GSMEM_BYTES>>>(
        txh, txl, inwh, inwl, h, 512, DLLM, DMODEL, 2 | 4, inb, SP);
    gemm_tc<<<dim3(DLLM / 128, 512 / 128), 256, GSMEM_BYTES>>>(
        vxh, vxl, inwh, inwl, h, 512, DLLM, DMODEL, 2 | 4, inb, SP + ST);

    for (int l = 0; l < 2; l++) {
        rmsnorm_split_kernel<<<NTOK, 256>>>(h, ln1 + (size_t)l * DLLM, xnh, xnl);
        gemm_tc<<<dim3(DLLM / 128, NTOK / 128), 256, GSMEM_BYTES>>>(
            xnh, xnl, BS + BO_QH + (size_t)l * W4, BS + BO_QL + (size_t)l * W4,
            q, NTOK, DLLM, DLLM, 0, nullptr, 0);
        gemm_tc<<<dim3(DLLM / 128, NTOK / 128), 256, GSMEM_BYTES>>>(
            xnh, xnl, BS + BO_KH + (size_t)l * W4, BS + BO_KL + (size_t)l * W4,
            k, NTOK, DLLM, DLLM, 0, nullptr, 0);
        gemm_tc<<<dim3(DLLM / 128, NTOK / 128), 256, GSMEM_BYTES>>>(
            xnh, xnl, BS + BO_VH + (size_t)l * W4, BS + BO_VL + (size_t)l * W4,
            v, NTOK, DLLM, DLLM, 0, nullptr, 0);
        rope_apply_kernel<<<(NTOK * NH * 64 + 255) / 256, 256>>>(q, k, cosb, sinb);
        attention_kernel<<<dim3(SEQ / 8, NH, B_), 256>>>(q, k, v, att);
        split_kernel<<<(int)((SZ_TOKD + 255) / 256), 256>>>(att, ath, atl, SZ_TOKD);
        gemm_tc<<<dim3(DLLM / 128, NTOK / 128), 256, GSMEM_BYTES>>>(
            ath, atl, BS + BO_OH + (size_t)l * W4, BS + BO_OL + (size_t)l * W4,
            h, NTOK, DLLM, DLLM, 1, nullptr, 0);

        rmsnorm_split_kernel<<<NTOK, 256>>>(h, ln2 + (size_t)l * DLLM, xnh, xnl);
        gemm_tc<<<dim3(DFF / 128, NTOK / 128), 256, GSMEM_BYTES>>>(
            xnh, xnl, BS + BO_GWH + (size_t)l * WF, BS + BO_GWL + (size_t)l * WF,
            gbuf, NTOK, DFF, DLLM, 0, nullptr, 0);
        gemm_tc<<<dim3(DFF / 128, NTOK / 128), 256, GSMEM_BYTES>>>(
            xnh, xnl, BS + BO_UWH + (size_t)l * WF, BS + BO_UWL + (size_t)l * WF,
            ubuf, NTOK, DFF, DLLM, 0, nullptr, 0);
        silu_mul_split_kernel<<<(int)((SZ_FF + 255) / 256), 256>>>(gbuf, ubuf, gh, gl, SZ_FF);
        gemm_tc<<<dim3(DLLM / 128, NTOK / 128), 256, GSMEM_BYTES>>>(
            gh, gl, BS + BO_DWH + (size_t)l * WF, BS + BO_DWL + (size_t)l * WF,
            h, NTOK, DLLM, DFF, 1, nullptr, 0);
    }

    rmsnorm_kernel<<<NTOK, 256>>>(h, fnw, xn);
    pool_kernel<<<(B_ * DLLM + 255) / 256, 256>>>(xn, pooled);
    head1_kernel<<<B_, 768>>>(pooled, o1W, o1b, y1);
    head2_kernel<<<B_, 256>>>(y1, o2W, o2b, out);
}

// round 8
// speedup vs baseline: 2.3993x; 1.0586x over previous
#include <cuda_runtime.h>
#include <cuda_bf16.h>
#include <math.h>
#include <stdint.h>

#define B_    8
#define SP    128
#define ST    64
#define SV    64
#define SEQ   256
#define DMODEL 768
#define DLLM  4096
#define NH    32
#define HD    128
#define DFF   11008
#define NTOK  (B_*SEQ)
#define QKVS  (3*DLLM)        // 12288, fused qkv row stride
#define GUS   (2*DFF)         // 22016, fused gate/up row stride
#define EPS   1e-5f

// ---------------- fp32 scratch ----------------
#define SZ_TOKD ((size_t)NTOK*DLLM)
#define SZ_FF   ((size_t)NTOK*DFF)
#define OFF_H    ((size_t)0)
#define OFF_XN   (SZ_TOKD)
#define OFF_QKV  (2*SZ_TOKD)                 // [NTOK, 12288]
#define OFF_ATT  (5*SZ_TOKD)
#define OFF_GU   (6*SZ_TOKD)                 // [NTOK, 22016]
#define OFF_COS  (OFF_GU + 2*SZ_FF)
#define OFF_SIN  (OFF_COS + (size_t)SEQ*64)
#define OFF_POOL (OFF_SIN + (size_t)SEQ*64)
#define OFF_Y1   (OFF_POOL + (size_t)B_*DLLM)
#define SCRATCH_TOTAL (OFF_Y1 + (size_t)B_*768)
__device__ float g_scratch[SCRATCH_TOTAL];

// ---------------- bf16 scratch ----------------
#define W4 ((size_t)DLLM*DLLM)
#define WF ((size_t)DLLM*DFF)
#define SZ_TV  ((size_t)512*DMODEL)
#define SZ_INW ((size_t)DMODEL*DLLM)
#define BO_XNH  ((size_t)0)
#define BO_XNL  (BO_XNH + SZ_TOKD)
#define BO_ATH  (BO_XNL + SZ_TOKD)
#define BO_ATL  (BO_ATH + SZ_TOKD)
#define BO_GH   (BO_ATL + SZ_TOKD)
#define BO_GL   (BO_GH + SZ_FF)
#define BO_TXH  (BO_GL + SZ_FF)
#define BO_TXL  (BO_TXH + SZ_TV)
#define BO_VXH  (BO_TXL + SZ_TV)
#define BO_VXL  (BO_VXH + SZ_TV)
#define BO_INWH (BO_VXL + SZ_TV)
#define BO_INWL (BO_INWH + SZ_INW)
#define BO_QKVH (BO_INWL + SZ_INW)           // per layer: 3*W4 (Wq^T,Wk^T,Wv^T)
#define BO_QKVL (BO_QKVH + 6*W4)
#define BO_OH   (BO_QKVL + 6*W4)             // per layer: W4
#define BO_OL   (BO_OH + 2*W4)
#define BO_GUH  (BO_OL + 2*W4)               // per layer: 2*WF (Wg^T,Wu^T)
#define BO_GUL  (BO_GUH + 4*WF)
#define BO_DWH  (BO_GUL + 4*WF)
#define BO_DWL  (BO_DWH + 2*WF)
#define BF_TOTAL (BO_DWL + 2*WF)
__device__ __align__(256) __nv_bfloat16 g_bf[BF_TOTAL];

// ---------------- helpers ----------------
__device__ __forceinline__ uint32_t smem_u32(const void* p) {
    uint32_t a;
    asm("{ .reg .u64 t; cvta.to.shared.u64 t, %1; cvt.u32.u64 %0, t; }" : "=r"(a) : "l"(p));
    return a;
}
__device__ __forceinline__ void cp16(uint32_t d, const void* s) {
    asm volatile("cp.async.cg.shared.global [%0], [%1], 16;" :: "r"(d), "l"(s));
}
__device__ __forceinline__ void split_bf(float x, __nv_bfloat16& h, __nv_bfloat16& l) {
    h = __float2bfloat16_rn(x);
    l = __float2bfloat16_rn(x - __bfloat162float(h));
}
__device__ __forceinline__ void mma_bf16(float* c,
    uint32_t a0, uint32_t a1, uint32_t a2, uint32_t a3, uint32_t b0, uint32_t b1) {
    asm volatile(
        "mma.sync.aligned.m16n8k16.row.col.f32.bf16.bf16.f32 "
        "{%0,%1,%2,%3}, {%4,%5,%6,%7}, {%8,%9}, {%0,%1,%2,%3};"
        : "+f"(c[0]), "+f"(c[1]), "+f"(c[2]), "+f"(c[3])
        : "r"(a0), "r"(a1), "r"(a2), "r"(a3), "r"(b0), "r"(b1));
}
__device__ __forceinline__ void ldm_x4(uint32_t& r0, uint32_t& r1,
                                       uint32_t& r2, uint32_t& r3, uint32_t a) {
    asm volatile("ldmatrix.sync.aligned.m8n8.x4.shared.b16 {%0,%1,%2,%3}, [%4];"
        : "=r"(r0), "=r"(r1), "=r"(r2), "=r"(r3) : "r"(a));
}

// ---------------------------------------------------------------------------
// bf16-split GEMM via mma.sync + ldmatrix.
// C[M,N] = A[M,K] @ W[K,N]; A=Ah+Al [M,K] bf16; W^T=Bh+Bl [N,K] bf16.
// 3 passes AhBh + AhBl + AlBh, fp32 accum. BM=BN=128, BK=32, 3-stage cp.async.
// flags: 1 accumulate, 2 bias, 4 row remap. M%128==0, N%128==0, K%32==0.
// ---------------------------------------------------------------------------
#define TPITCH 40
#define TILE_E (128*TPITCH)
#define STAGE_E (4*TILE_E)
#define GSMEM_BYTES (3*STAGE_E*2)

__global__ __launch_bounds__(256, 1) void gemm_tc(
    const __nv_bfloat16* __restrict__ Ah, const __nv_bfloat16* __restrict__ Al,
    const __nv_bfloat16* __restrict__ Bh, const __nv_bfloat16* __restrict__ Bl,
    float* __restrict__ C, int M, int N, int K,
    int flags, const float* __restrict__ bias, int map_base)
{
    extern __shared__ __nv_bfloat16 sm[];
    const int tid = threadIdx.x;
    const int wid = tid >> 5, lane = tid & 31;
    const int wm = wid & 3, wn = wid >> 2;
    const int m0 = blockIdx.y * 128, n0 = blockIdx.x * 128;
    const int gr = lane >> 2, qc = lane & 3;
    const uint32_t smbase = smem_u32(sm);

    // ldmatrix per-lane byte offsets within a tile
    const uint32_t aoff = (uint32_t)(((wm * 32 + (lane & 15)) * TPITCH + ((lane >> 4) << 3)) * 2);
    const uint32_t boff = (uint32_t)(((wn * 64 + ((lane >> 4) << 3) + (lane & 7)) * TPITCH
                                      + (((lane >> 3) & 1) << 3)) * 2);

    // Loader: 2048 16B chunks / stage, 8 per thread
    const __nv_bfloat16* gp[8];
    uint32_t soff[8];
#pragma unroll
    for (int i = 0; i < 8; i++) {
        int c = tid + i * 256;
        int tile = c >> 9, local = c & 511, row = local >> 2, sub = local & 3;
        const __nv_bfloat16* base = (tile == 0) ? Ah : (tile == 1) ? Al
                                  : (tile == 2) ? Bh : Bl;
        int grow = ((tile < 2) ? m0 : n0) + row;
        gp[i] = base + (size_t)grow * K + sub * 8;
        soff[i] = (uint32_t)((tile * TILE_E + row * TPITCH + sub * 8) * 2);
    }

#define LOAD_STAGE(s_) do { \
    uint32_t sb_ = smbase + (uint32_t)(((s_) % 3) * STAGE_E * 2); \
    _Pragma("unroll") \
    for (int i_ = 0; i_ < 8; i_++) \
        cp16(sb_ + soff[i_], gp[i_] + (size_t)(s_) * 32); \
    asm volatile("cp.async.commit_group;" ::: "memory"); \
} while (0)

    const int S = K / 32;
    LOAD_STAGE(0);
    LOAD_STAGE(1);

    float acc[2][8][4];
#pragma unroll
    for (int t = 0; t < 2; t++)
#pragma unroll
        for (int n = 0; n < 8; n++)
#pragma unroll
            for (int e = 0; e < 4; e++) acc[t][n][e] = 0.f;

    for (int s = 0; s < S; s++) {
        asm volatile("cp.async.wait_group 1;" ::: "memory");
        __syncthreads();
        if (s + 2 < S) { LOAD_STAGE(s + 2); }
        else { asm volatile("cp.async.commit_group;" ::: "memory"); }

        const uint32_t stg = smbase + (uint32_t)((s % 3) * STAGE_E * 2);
        const uint32_t tAh = stg;
        const uint32_t tAl = stg + TILE_E * 2;
        const uint32_t tBh = stg + 2 * TILE_E * 2;
        const uint32_t tBl = stg + 3 * TILE_E * 2;

#pragma unroll
        for (int kk = 0; kk < 32; kk += 16) {
            uint32_t ah[2][4], al[2][4], bh[8][2], bl[8][2];
#pragma unroll
            for (int t = 0; t < 2; t++) {
                uint32_t off = aoff + (uint32_t)((t * 16 * TPITCH + kk) * 2);
                ldm_x4(ah[t][0], ah[t][1], ah[t][2], ah[t][3], tAh + off);
                ldm_x4(al[t][0], al[t][1], al[t][2], al[t][3], tAl + off);
            }
#pragma unroll
            for (int j = 0; j < 4; j++) {
                uint32_t off = boff + (uint32_t)((j * 16 * TPITCH + kk) * 2);
                ldm_x4(bh[2*j][0], bh[2*j][1], bh[2*j+1][0], bh[2*j+1][1], tBh + off);
                ldm_x4(bl[2*j][0], bl[2*j][1], bl[2*j+1][0], bl[2*j+1][1], tBl + off);
            }
#pragma unroll
            for (int t = 0; t < 2; t++)
#pragma unroll
                for (int n = 0; n < 8; n++) {
                    mma_bf16(acc[t][n], ah[t][0], ah[t][1], ah[t][2], ah[t][3],
                             bh[n][0], bh[n][1]);
                    mma_bf16(acc[t][n], ah[t][0], ah[t][1], ah[t][2], ah[t][3],
                             bl[n][0], bl[n][1]);
                    mma_bf16(acc[t][n], al[t][0], al[t][1], al[t][2], al[t][3],
                             bh[n][0], bh[n][1]);
                }
        }
    }

    // Epilogue
#pragma unroll
    for (int t = 0; t < 2; t++) {
#pragma unroll
        for (int half = 0; half < 2; half++) {
            int grow = m0 + wm * 32 + t * 16 + gr + half * 8;
            int orow = (flags & 4) ? ((grow >> 6) * SEQ + map_base + (grow & 63)) : grow;
            float* crow = C + (size_t)orow * N;
#pragma unroll
            for (int n = 0; n < 8; n++) {
                int col = n0 + wn * 64 + n * 8 + qc * 2;
                float2 v;
                v.x = acc[t][n][half * 2 + 0];
                v.y = acc[t][n][half * 2 + 1];
                if (flags & 2) {
                    float2 b2 = *reinterpret_cast<const float2*>(bias + col);
                    v.x += b2.x; v.y += b2.y;
                }
                if (flags & 1) {
                    float2 o = *reinterpret_cast<const float2*>(crow + col);
                    v.x += o.x; v.y += o.y;
                }
                *reinterpret_cast<float2*>(crow + col) = v;
            }
        }
    }
#undef LOAD_STAGE
}

// ---------------- transpose + split: src[K,N] fp32 -> [N,K] bf16 hi/lo ------
__global__ void transpose_split_kernel(
    const float* __restrict__ src,
    __nv_bfloat16* __restrict__ dhi, __nv_bfloat16* __restrict__ dlo,
    int K, int N)
{
    __shared__ float tile[32][33];
    const int n0 = blockIdx.x * 32, k0 = blockIdx.y * 32;
    const int tx = threadIdx.x, ty = threadIdx.y;
#pragma unroll
    for (int i = 0; i < 32; i += 8)
        tile[ty + i][tx] = src[(size_t)(k0 + ty + i) * N + n0 + tx];
    __syncthreads();
#pragma unroll
    for (int i = 0; i < 32; i += 8) {
        float v = tile[tx][ty + i];
        __nv_bfloat16 h, l;
        split_bf(v, h, l);
        size_t idx = (size_t)(n0 + ty + i) * K + k0 + tx;
        dhi[idx] = h; dlo[idx] = l;
    }
}

__global__ void split_kernel(const float* __restrict__ src,
                             __nv_bfloat16* __restrict__ hi,
                             __nv_bfloat16* __restrict__ lo, size_t n)
{
    size_t idx = (size_t)blockIdx.x * blockDim.x + threadIdx.x;
    if (idx >= n) return;
    __nv_bfloat16 h, l;
    split_bf(src[idx], h, l);
    hi[idx] = h; lo[idx] = l;
}

__global__ void rope_table_kernel(float* __restrict__ cosb, float* __restrict__ sinb)
{
    int idx = blockIdx.x * blockDim.x + threadIdx.x;
    if (idx >= SEQ * 64) return;
    int s = idx >> 6, i = idx & 63;
    double inv = exp(-((double)(2 * i) / 128.0) * log(10000.0));
    double ang = (double)s * inv;
    cosb[idx] = (float)cos(ang);
    sinb[idx] = (float)sin(ang);
}

__global__ void embed_gather_kernel(const int* __restrict__ ids,
                                    const float* __restrict__ table,
                                    float* __restrict__ h)
{
    int idx = blockIdx.x * blockDim.x + threadIdx.x;
    if (idx >= B_ * SP * DLLM) return;
    int d = idx & (DLLM - 1);
    int r = (idx >> 12) & (SP - 1);
    int b = idx >> 19;
    int id = ids[b * SP + r];
    h[((size_t)(b * SEQ + r)) * DLLM + d] = table[(size_t)id * DLLM + d];
}

__global__ __launch_bounds__(256) void rmsnorm_kernel(
    const float* __restrict__ x, const float* __restrict__ w, float* __restrict__ out)
{
    int t = blockIdx.x;
    const float4* xr = reinterpret_cast<const float4*>(x + (size_t)t * DLLM);
    float4 vals[4];
    float s = 0.f;
#pragma unroll
    for (int j = 0; j < 4; j++) {
        float4 v = xr[threadIdx.x + j * 256];
        vals[j] = v;
        s += v.x * v.x + v.y * v.y + v.z * v.z + v.w * v.w;
    }
#pragma unroll
    for (int off = 16; off > 0; off >>= 1) s += __shfl_xor_sync(0xffffffffu, s, off);
    __shared__ float red[8];
    __shared__ float sscale;
    if ((threadIdx.x & 31) == 0) red[threadIdx.x >> 5] = s;
    __syncthreads();
    if (threadIdx.x == 0) {
        float r = 0.f;
#pragma unroll
        for (int i = 0; i < 8; i++) r += red[i];
        sscale = rsqrtf(r * (1.0f / DLLM) + EPS);
    }
    __syncthreads();
    float sc = sscale;
    const float4* w4 = reinterpret_cast<const float4*>(w);
    float4* o4 = reinterpret_cast<float4*>(out + (size_t)t * DLLM);
#pragma unroll
    for (int j = 0; j < 4; j++) {
        float4 v = vals[j];
        float4 wv = w4[threadIdx.x + j * 256];
        o4[threadIdx.x + j * 256] = make_float4(
            v.x * sc * wv.x, v.y * sc * wv.y, v.z * sc * wv.z, v.w * sc * wv.w);
    }
}

__global__ __launch_bounds__(256) void rmsnorm_split_kernel(
    const float* __restrict__ x, const float* __restrict__ w,
    __nv_bfloat16* __restrict__ ohi, __nv_bfloat16* __restrict__ olo)
{
    int t = blockIdx.x;
    const float4* xr = reinterpret_cast<const float4*>(x + (size_t)t * DLLM);
    float4 vals[4];
    float s = 0.f;
#pragma unroll
    for (int j = 0; j < 4; j++) {
        float4 v = xr[threadIdx.x + j * 256];
        vals[j] = v;
        s += v.x * v.x + v.y * v.y + v.z * v.z + v.w * v.w;
    }
#pragma unroll
    for (int off = 16; off > 0; off >>= 1) s += __shfl_xor_sync(0xffffffffu, s, off);
    __shared__ float red[8];
    __shared__ float sscale;
    if ((threadIdx.x & 31) == 0) red[threadIdx.x >> 5] = s;
    __syncthreads();
    if (threadIdx.x == 0) {
        float r = 0.f;
#pragma unroll
        for (int i = 0; i < 8; i++) r += red[i];
        sscale = rsqrtf(r * (1.0f / DLLM) + EPS);
    }
    __syncthreads();
    float sc = sscale;
    const float4* w4 = reinterpret_cast<const float4*>(w);
    size_t base = (size_t)t * DLLM;
#pragma unroll
    for (int j = 0; j < 4; j++) {
        float4 v = vals[j];
        float4 wv = w4[threadIdx.x + j * 256];
        float rr[4] = { v.x * sc * wv.x, v.y * sc * wv.y, v.z * sc * wv.z, v.w * sc * wv.w };
        size_t o = base + ((size_t)threadIdx.x + j * 256) * 4;
#pragma unroll
        for (int e = 0; e < 4; e++) {
            __nv_bfloat16 h, l;
            split_bf(rr[e], h, l);
            ohi[o + e] = h; olo[o + e] = l;
        }
    }
}

// RoPE on fused qkv buffer (row stride QKVS; q at +0, k at +DLLM)
__global__ void rope_apply_kernel(float* __restrict__ qkv,
                                  const float* __restrict__ cosb,
                                  const float* __restrict__ sinb)
{
    int idx = blockIdx.x * blockDim.x + threadIdx.x;
    if (idx >= NTOK * NH * 64) return;
    int i = idx & 63;
    int h = (idx >> 6) & (NH - 1);
    int t = idx >> 11;
    int s = t & (SEQ - 1);
    float c = cosb[s * 64 + i];
    float sn = sinb[s * 64 + i];
    size_t base = (size_t)t * QKVS + h * HD + i;
    float x1 = qkv[base], x2 = qkv[base + 64];
    qkv[base]      = x1 * c - x2 * sn;
    qkv[base + 64] = x2 * c + x1 * sn;
    size_t kb = base + DLLM;
    x1 = qkv[kb]; x2 = qkv[kb + 64];
    qkv[kb]      = x1 * c - x2 * sn;
    qkv[kb + 64] = x2 * c + x1 * sn;
}

__global__ __launch_bounds__(256) void attention_kernel(
    const float* __restrict__ qkv, float* __restrict__ out)
{
    __shared__ float sc[8][SEQ];
    const int b = blockIdx.z, hh = blockIdx.y;
    const int w = threadIdx.x >> 5, lane = threadIdx.x & 31;
    const int qi = blockIdx.x * 8 + w;
    const float scale = 0.088388347648318447f;

    const float* qrow = qkv + (size_t)(b * SEQ + qi) * QKVS + hh * HD;
    float4 qv = reinterpret_cast<const float4*>(qrow)[lane];

    const float* kbase = qkv + (size_t)b * SEQ * QKVS + DLLM + hh * HD;
    for (int kk = 0; kk <= qi; kk++) {
        float4 kv = reinterpret_cast<const float4*>(kbase + (size_t)kk * QKVS)[lane];
        float d = qv.x * kv.x + qv.y * kv.y + qv.z * kv.z + qv.w * kv.w;
#pragma unroll
        for (int off = 16; off > 0; off >>= 1) d += __shfl_xor_sync(0xffffffffu, d, off);
        if (lane == 0) sc[w][kk] = d * scale;
    }
    __syncwarp();

    float m = -1e30f;
    for (int kk = lane; kk <= qi; kk += 32) m = fmaxf(m, sc[w][kk]);
#pragma unroll
    for (int off = 16; off > 0; off >>= 1) m = fmaxf(m, __shfl_xor_sync(0xffffffffu, m, off));

    float ssum = 0.f;
    for (int kk = lane; kk <= qi; kk += 32) {
        float p = expf(sc[w][kk] - m);
        sc[w][kk] = p;
        ssum += p;
    }
#pragma unroll
    for (int off = 16; off > 0; off >>= 1) ssum += __shfl_xor_sync(0xffffffffu, ssum, off);
    __syncwarp();
    float inv = 1.0f / ssum;

    const float* vbase = qkv + (size_t)b * SEQ * QKVS + 2 * DLLM + hh * HD;
    float4 acc = make_float4(0.f, 0.f, 0.f, 0.f);
    for (int kk = 0; kk <= qi; kk++) {
        float p = sc[w][kk];
        float4 vv = reinterpret_cast<const float4*>(vbase + (size_t)kk * QKVS)[lane];
        acc.x += p * vv.x; acc.y += p * vv.y;
        acc.z += p * vv.z; acc.w += p * vv.w;
    }
    float* orow = out + (size_t)(b * SEQ + qi) * DLLM + hh * HD;
    reinterpret_cast<float4*>(orow)[lane] =
        make_float4(acc.x * inv, acc.y * inv, acc.z * inv, acc.w * inv);
}

// SwiGLU from fused gu buffer: grid (DFF/256, NTOK)
__global__ void silu_mul_split_kernel(const float* __restrict__ gu,
                                      __nv_bfloat16* __restrict__ ohi,
                                      __nv_bfloat16* __restrict__ olo)
{
    int j = blockIdx.x * 256 + threadIdx.x;
    int t = blockIdx.y;
    const float* row = gu + (size_t)t * GUS;
    float x = row[j];
    float r = (x / (1.0f + expf(-x))) * row[DFF + j];
    __nv_bfloat16 h, l;
    split_bf(r, h, l);
    size_t o = (size_t)t * DFF + j;
    ohi[o] = h; olo[o] = l;
}

__global__ void pool_kernel(const float* __restrict__ xn, float* __restrict__ pooled)
{
    int idx = blockIdx.x * blockDim.x + threadIdx.x;
    if (idx >= B_ * DLLM) return;
    int b = idx >> 12, d = idx & (DLLM - 1);
    float s = 0.f;
    for (int t = 0; t < SEQ; t++)
        s += xn[(size_t)(b * SEQ + t) * DLLM + d];
    pooled[idx] = s * (1.0f / SEQ);
}

__global__ void head1_kernel(const float* __restrict__ pooled,
                             const float* __restrict__ W,
                             const float* __restrict__ bias,
                             float* __restrict__ y1)
{
    int b = blockIdx.x, j = threadIdx.x;
    const float* p = pooled + (size_t)b * DLLM;
    float s = bias[j];
    for (int i = 0; i < DLLM; i++) s += p[i] * W[(size_t)i * 768 + j];
    y1[b * 768 + j] = s;
}

__global__ void head2_kernel(const float* __restrict__ y1,
                             const float* __restrict__ W,
                             const float* __restrict__ bias,
                             float* __restrict__ out)
{
    int b = blockIdx.x;
    float s = 0.f;
    for (int j = threadIdx.x; j < 768; j += 256) s += y1[b * 768 + j] * W[j];
#pragma unroll
    for (int off = 16; off > 0; off >>= 1) s += __shfl_xor_sync(0xffffffffu, s, off);
    __shared__ float red[8];
    if ((threadIdx.x & 31) == 0) red[threadIdx.x >> 5] = s;
    __syncthreads();
    if (threadIdx.x == 0) {
        float r = 0.f;
#pragma unroll
        for (int i = 0; i < 8; i++) r += red[i];
        out[b] = r + bias[0];
    }
}

// ---------------------------------------------------------------------------
extern "C" void kernel_launch(void* const* d_in, const int* in_sizes, int n_in,
                              void* d_out, int out_size)
{
    const float* text  = (const float*)d_in[0];
    const float* vis   = (const float*)d_in[1];
    const int*   ids   = (const int*)  d_in[2];
    const float* inW   = (const float*)d_in[3];
    const float* inb   = (const float*)d_in[4];
    const float* etab  = (const float*)d_in[5];
    const float* Wq    = (const float*)d_in[6];
    const float* Wk    = (const float*)d_in[7];
    const float* Wv    = (const float*)d_in[8];
    const float* Wo    = (const float*)d_in[9];
    const float* ln1   = (const float*)d_in[10];
    const float* ln2   = (const float*)d_in[11];
    const float* Wg    = (const float*)d_in[12];
    const float* Wu    = (const float*)d_in[13];
    const float* Wd    = (const float*)d_in[14];
    const float* fnw   = (const float*)d_in[15];
    const float* o1W   = (const float*)d_in[16];
    const float* o1b   = (const float*)d_in[17];
    const float* o2W   = (const float*)d_in[18];
    const float* o2b   = (const float*)d_in[19];
    float* out = (float*)d_out;

    cudaFuncSetAttribute(gemm_tc, cudaFuncAttributeMaxDynamicSharedMemorySize,
                         GSMEM_BYTES);

    float* S = nullptr;
    cudaGetSymbolAddress((void**)&S, g_scratch);
    __nv_bfloat16* BS = nullptr;
    cudaGetSymbolAddress((void**)&BS, g_bf);

    float* h    = S + OFF_H;
    float* xn   = S + OFF_XN;
    float* qkv  = S + OFF_QKV;
    float* att  = S + OFF_ATT;
    float* gu   = S + OFF_GU;
    float* cosb = S + OFF_COS;
    float* sinb = S + OFF_SIN;
    float* pooled = S + OFF_POOL;
    float* y1   = S + OFF_Y1;

    __nv_bfloat16 *xnh = BS + BO_XNH, *xnl = BS + BO_XNL;
    __nv_bfloat16 *ath = BS + BO_ATH, *atl = BS + BO_ATL;
    __nv_bfloat16 *gh  = BS + BO_GH,  *gl  = BS + BO_GL;
    __nv_bfloat16 *txh = BS + BO_TXH, *txl = BS + BO_TXL;
    __nv_bfloat16 *vxh = BS + BO_VXH, *vxl = BS + BO_VXL;
    __nv_bfloat16 *inwh = BS + BO_INWH, *inwl = BS + BO_INWL;

    dim3 t32(32, 8);

    rope_table_kernel<<<(SEQ * 64 + 255) / 256, 256>>>(cosb, sinb);

    transpose_split_kernel<<<dim3(DLLM / 32, DMODEL / 32), t32>>>(inW, inwh, inwl, DMODEL, DLLM);
    for (int l = 0; l < 2; l++) {
        // QKV weights contiguous per layer: [Wq^T; Wk^T; Wv^T] = [12288, 4096]
        transpose_split_kernel<<<dim3(DLLM / 32, DLLM / 32), t32>>>(
            Wq + (size_t)l * W4, BS + BO_QKVH + (size_t)l * 3 * W4,
            BS + BO_QKVL + (size_t)l * 3 * W4, DLLM, DLLM);
        transpose_split_kernel<<<dim3(DLLM / 32, DLLM / 32), t32>>>(
            Wk + (size_t)l * W4, BS + BO_QKVH + (size_t)l * 3 * W4 + W4,
            BS + BO_QKVL + (size_t)l * 3 * W4 + W4, DLLM, DLLM);
        transpose_split_kernel<<<dim3(DLLM / 32, DLLM / 32), t32>>>(
            Wv + (size_t)l * W4, BS + BO_QKVH + (size_t)l * 3 * W4 + 2 * W4,
            BS + BO_QKVL + (size_t)l * 3 * W4 + 2 * W4, DLLM, DLLM);
        transpose_split_kernel<<<dim3(DLLM / 32, DLLM / 32), t32>>>(
            Wo + (size_t)l * W4, BS + BO_OH + (size_t)l * W4,
            BS + BO_OL + (size_t)l * W4, DLLM, DLLM);
        // gate/up contiguous per layer: [Wg^T; Wu^T] = [22016, 4096]
        transpose_split_kernel<<<dim3(DFF / 32, DLLM / 32), t32>>>(
            Wg + (size_t)l * WF, BS + BO_GUH + (size_t)l * 2 * WF,
            BS + BO_GUL + (size_t)l * 2 * WF, DLLM, DFF);
        transpose_split_kernel<<<dim3(DFF / 32, DLLM / 32), t32>>>(
            Wu + (size_t)l * WF, BS + BO_GUH + (size_t)l * 2 * WF + WF,
            BS + BO_GUL + (size_t)l * 2 * WF + WF, DLLM, DFF);
        transpose_split_kernel<<<dim3(DLLM / 32, DFF / 32), t32>>>(
            Wd + (size_t)l * WF, BS + BO_DWH + (size_t)l * WF,
            BS + BO_DWL + (size_t)l * WF, DFF, DLLM);
    }

    embed_gather_kernel<<<(B_ * SP * DLLM + 255) / 256, 256>>>(ids, etab, h);
    split_kernel<<<(int)((SZ_TV + 255) / 256), 256>>>(text, txh, txl, SZ_TV);
    split_kernel<<<(int)((SZ_TV + 255) / 256), 256>>>(vis, vxh, vxl, SZ_TV);
    gemm_tc<<<dim3(DLLM / 128, 512 / 128), 256, GSMEM_BYTES>>>(
        txh, txl, inwh, inwl, h, 512, DLLM, DMODEL, 2 | 4, inb, SP);
    gemm_tc<<<dim3(DLLM / 128, 512 / 128), 256, GSMEM_BYTES>>>(
        vxh, vxl, inwh, inwl, h, 512, DLLM, DMODEL, 2 | 4, inb, SP + ST);

    for (int l = 0; l < 2; l++) {
        rmsnorm_split_kernel<<<NTOK, 256>>>(h, ln1 + (size_t)l * DLLM, xnh, xnl);
        // fused QKV: [NTOK, 12288]
        gemm_tc<<<dim3(QKVS / 128, NTOK / 128), 256, GSMEM_BYTES>>>(
            xnh, xnl, BS + BO_QKVH + (size_t)l * 3 * W4, BS + BO_QKVL + (size_t)l * 3 * W4,
            qkv, NTOK, QKVS, DLLM, 0, nullptr, 0);
        rope_apply_kernel<<<(NTOK * NH * 64 + 255) / 256, 256>>>(qkv, cosb, sinb);
        attention_kernel<<<dim3(SEQ / 8, NH, B_), 256>>>(qkv, att);
        split_kernel<<<(int)((SZ_TOKD + 255) / 256), 256>>>(att, ath, atl, SZ_TOKD);
        gemm_tc<<<dim3(DLLM / 128, NTOK / 128), 256, GSMEM_BYTES>>>(
            ath, atl, BS + BO_OH + (size_t)l * W4, BS + BO_OL + (size_t)l * W4,
            h, NTOK, DLLM, DLLM, 1, nullptr, 0);

        rmsnorm_split_kernel<<<NTOK, 256>>>(h, ln2 + (size_t)l * DLLM, xnh, xnl);
        // fused gate+up: [NTOK, 22016]
        gemm_tc<<<dim3(GUS / 128, NTOK / 128), 256, GSMEM_BYTES>>>(
            xnh, xnl, BS + BO_GUH + (size_t)l * 2 * WF, BS + BO_GUL + (size_t)l * 2 * WF,
            gu, NTOK, GUS, DLLM, 0, nullptr, 0);
        silu_mul_split_kernel<<<dim3(DFF / 256, NTOK), 256>>>(gu, gh, gl);
        gemm_tc<<<dim3(DLLM / 128, NTOK / 128), 256, GSMEM_BYTES>>>(
            gh, gl, BS + BO_DWH + (size_t)l * WF, BS + BO_DWL + (size_t)l * WF,
            h, NTOK, DLLM, DFF, 1, nullptr, 0);
    }

    rmsnorm_kernel<<<NTOK, 256>>>(h, fnw, xn);
    pool_kernel<<<(B_ * DLLM + 255) / 256, 256>>>(xn, pooled);
    head1_kernel<<<B_, 768>>>(pooled, o1W, o1b, y1);
    head2_kernel<<<B_, 256>>>(y1, o2W, o2b, out);
}

// round 9
// speedup vs baseline: 2.6630x; 1.1099x over previous
#include <cuda_runtime.h>
#include <cuda_bf16.h>
#include <math.h>
#include <stdint.h>

#define B_    8
#define SP    128
#define ST    64
#define SV    64
#define SEQ   256
#define DMODEL 768
#define DLLM  4096
#define NH    32
#define HD    128
#define DFF   11008
#define NTOK  (B_*SEQ)
#define QKVS  (3*DLLM)
#define GUS   (2*DFF)
#define EPS   1e-5f

// ---------------- fp32 scratch ----------------
#define SZ_TOKD ((size_t)NTOK*DLLM)
#define SZ_FF   ((size_t)NTOK*DFF)
#define OFF_H    ((size_t)0)
#define OFF_XN   (SZ_TOKD)
#define OFF_QKV  (2*SZ_TOKD)                 // [NTOK, 12288]
#define OFF_GU   (5*SZ_TOKD)                 // [NTOK, 22016]
#define OFF_COS  (OFF_GU + 2*SZ_FF)
#define OFF_SIN  (OFF_COS + (size_t)SEQ*64)
#define OFF_POOL (OFF_SIN + (size_t)SEQ*64)
#define OFF_Y1   (OFF_POOL + (size_t)B_*DLLM)
#define SCRATCH_TOTAL (OFF_Y1 + (size_t)B_*768)
__device__ float g_scratch[SCRATCH_TOTAL];

// ---------------- bf16 scratch ----------------
#define W4 ((size_t)DLLM*DLLM)
#define WF ((size_t)DLLM*DFF)
#define SZ_TV  ((size_t)512*DMODEL)
#define SZ_INW ((size_t)DMODEL*DLLM)
#define BO_XNH  ((size_t)0)
#define BO_XNL  (BO_XNH + SZ_TOKD)
#define BO_ATH  (BO_XNL + SZ_TOKD)
#define BO_ATL  (BO_ATH + SZ_TOKD)
#define BO_GH   (BO_ATL + SZ_TOKD)
#define BO_GL   (BO_GH + SZ_FF)
#define BO_TXH  (BO_GL + SZ_FF)
#define BO_TXL  (BO_TXH + SZ_TV)
#define BO_VXH  (BO_TXL + SZ_TV)
#define BO_VXL  (BO_VXH + SZ_TV)
#define BO_INWH (BO_VXL + SZ_TV)
#define BO_INWL (BO_INWH + SZ_INW)
#define BO_QKVH (BO_INWL + SZ_INW)
#define BO_QKVL (BO_QKVH + 6*W4)
#define BO_OH   (BO_QKVL + 6*W4)
#define BO_OL   (BO_OH + 2*W4)
#define BO_GUH  (BO_OL + 2*W4)
#define BO_GUL  (BO_GUH + 4*WF)
#define BO_DWH  (BO_GUL + 4*WF)
#define BO_DWL  (BO_DWH + 2*WF)
#define BF_TOTAL (BO_DWL + 2*WF)
__device__ __align__(256) __nv_bfloat16 g_bf[BF_TOTAL];

// ---------------- helpers ----------------
__device__ __forceinline__ uint32_t smem_u32(const void* p) {
    uint32_t a;
    asm("{ .reg .u64 t; cvta.to.shared.u64 t, %1; cvt.u32.u64 %0, t; }" : "=r"(a) : "l"(p));
    return a;
}
__device__ __forceinline__ void cp16(uint32_t d, const void* s) {
    asm volatile("cp.async.cg.shared.global [%0], [%1], 16;" :: "r"(d), "l"(s));
}
__device__ __forceinline__ void split_bf(float x, __nv_bfloat16& h, __nv_bfloat16& l) {
    h = __float2bfloat16_rn(x);
    l = __float2bfloat16_rn(x - __bfloat162float(h));
}
__device__ __forceinline__ void mma_bf16(float* c,
    uint32_t a0, uint32_t a1, uint32_t a2, uint32_t a3, uint32_t b0, uint32_t b1) {
    asm volatile(
        "mma.sync.aligned.m16n8k16.row.col.f32.bf16.bf16.f32 "
        "{%0,%1,%2,%3}, {%4,%5,%6,%7}, {%8,%9}, {%0,%1,%2,%3};"
        : "+f"(c[0]), "+f"(c[1]), "+f"(c[2]), "+f"(c[3])
        : "r"(a0), "r"(a1), "r"(a2), "r"(a3), "r"(b0), "r"(b1));
}
__device__ __forceinline__ void ldm_x4(uint32_t& r0, uint32_t& r1,
                                       uint32_t& r2, uint32_t& r3, uint32_t a) {
    asm volatile("ldmatrix.sync.aligned.m8n8.x4.shared.b16 {%0,%1,%2,%3}, [%4];"
        : "=r"(r0), "=r"(r1), "=r"(r2), "=r"(r3) : "r"(a));
}

// ---------------------------------------------------------------------------
// bf16-split GEMM via mma.sync + ldmatrix. BM=128, BN=64, BK=32.
// C[M,N] = A[M,K] @ W[K,N]; A=Ah+Al [M,K] bf16; W^T=Bh+Bl [N,K] bf16.
// 3 passes AhBh + AhBl + AlBh, fp32 accum, 3-stage cp.async, 2 CTAs/SM.
// flags: 1 accumulate, 2 bias, 4 row remap. M%128==0, N%64==0, K%32==0.
// ---------------------------------------------------------------------------
#define TPITCH 40
#define O_AH 0
#define O_AL (128*TPITCH)
#define O_BH (256*TPITCH)
#define O_BL (320*TPITCH)
#define STAGE_E (384*TPITCH)          // 15360 elements
#define GSMEM_BYTES (3*STAGE_E*2)     // 92160 B

__global__ __launch_bounds__(256, 2) void gemm_tc(
    const __nv_bfloat16* __restrict__ Ah, const __nv_bfloat16* __restrict__ Al,
    const __nv_bfloat16* __restrict__ Bh, const __nv_bfloat16* __restrict__ Bl,
    float* __restrict__ C, int M, int N, int K,
    int flags, const float* __restrict__ bias, int map_base)
{
    extern __shared__ __nv_bfloat16 sm[];
    const int tid = threadIdx.x;
    const int wid = tid >> 5, lane = tid & 31;
    const int wm = wid & 3, wn = wid >> 2;          // 4 m-warps x 2 n-warps
    const int m0 = blockIdx.y * 128, n0 = blockIdx.x * 64;
    const int gr = lane >> 2, qc = lane & 3;
    const uint32_t smbase = smem_u32(sm);

    // ldmatrix per-lane byte offsets within a stage
    const uint32_t aoff = (uint32_t)(((wm * 32 + (lane & 15)) * TPITCH + ((lane >> 4) << 3)) * 2);
    const uint32_t boff = (uint32_t)(((wn * 32 + ((lane >> 4) << 3) + (lane & 7)) * TPITCH
                                      + (((lane >> 3) & 1) << 3)) * 2);

    // Loader: 1536 16B chunks / stage, 6 per thread
    const __nv_bfloat16* gp[6];
    uint32_t soff[6];
#pragma unroll
    for (int i = 0; i < 6; i++) {
        int c = tid + i * 256;
        const __nv_bfloat16* base; int row, tbase;
        if (c < 512)       { base = Ah; row = c >> 2;          tbase = O_AH; }
        else if (c < 1024) { base = Al; row = (c - 512) >> 2;  tbase = O_AL; }
        else if (c < 1280) { base = Bh; row = (c - 1024) >> 2; tbase = O_BH; }
        else               { base = Bl; row = (c - 1280) >> 2; tbase = O_BL; }
        int sub = c & 3;
        int grow = ((c < 1024) ? m0 : n0) + row;
        gp[i] = base + (size_t)grow * K + sub * 8;
        soff[i] = (uint32_t)((tbase + row * TPITCH + sub * 8) * 2);
    }

#define LOAD_STAGE(s_) do { \
    uint32_t sb_ = smbase + (uint32_t)(((s_) % 3) * STAGE_E * 2); \
    _Pragma("unroll") \
    for (int i_ = 0; i_ < 6; i_++) \
        cp16(sb_ + soff[i_], gp[i_] + (size_t)(s_) * 32); \
    asm volatile("cp.async.commit_group;" ::: "memory"); \
} while (0)

    const int S = K / 32;
    LOAD_STAGE(0);
    LOAD_STAGE(1);

    float acc[2][4][4];
#pragma unroll
    for (int t = 0; t < 2; t++)
#pragma unroll
        for (int n = 0; n < 4; n++)
#pragma unroll
            for (int e = 0; e < 4; e++) acc[t][n][e] = 0.f;

    for (int s = 0; s < S; s++) {
        asm volatile("cp.async.wait_group 1;" ::: "memory");
        __syncthreads();
        if (s + 2 < S) { LOAD_STAGE(s + 2); }
        else { asm volatile("cp.async.commit_group;" ::: "memory"); }

        const uint32_t stg = smbase + (uint32_t)((s % 3) * STAGE_E * 2);

#pragma unroll
        for (int kk = 0; kk < 32; kk += 16) {
            uint32_t ah[2][4], al[2][4], bh[4][2], bl[4][2];
#pragma unroll
            for (int t = 0; t < 2; t++) {
                uint32_t off = aoff + (uint32_t)((t * 16 * TPITCH + kk) * 2);
                ldm_x4(ah[t][0], ah[t][1], ah[t][2], ah[t][3], stg + O_AH * 2 + off);
                ldm_x4(al[t][0], al[t][1], al[t][2], al[t][3], stg + O_AL * 2 + off);
            }
#pragma unroll
            for (int j = 0; j < 2; j++) {
                uint32_t off = boff + (uint32_t)((j * 16 * TPITCH + kk) * 2);
                ldm_x4(bh[2*j][0], bh[2*j][1], bh[2*j+1][0], bh[2*j+1][1], stg + O_BH * 2 + off);
                ldm_x4(bl[2*j][0], bl[2*j][1], bl[2*j+1][0], bl[2*j+1][1], stg + O_BL * 2 + off);
            }
#pragma unroll
            for (int t = 0; t < 2; t++)
#pragma unroll
                for (int n = 0; n < 4; n++) {
                    mma_bf16(acc[t][n], ah[t][0], ah[t][1], ah[t][2], ah[t][3],
                             bh[n][0], bh[n][1]);
                    mma_bf16(acc[t][n], ah[t][0], ah[t][1], ah[t][2], ah[t][3],
                             bl[n][0], bl[n][1]);
                    mma_bf16(acc[t][n], al[t][0], al[t][1], al[t][2], al[t][3],
                             bh[n][0], bh[n][1]);
                }
        }
    }

    // Epilogue
#pragma unroll
    for (int t = 0; t < 2; t++) {
#pragma unroll
        for (int half = 0; half < 2; half++) {
            int grow = m0 + wm * 32 + t * 16 + gr + half * 8;
            int orow = (flags & 4) ? ((grow >> 6) * SEQ + map_base + (grow & 63)) : grow;
            float* crow = C + (size_t)orow * N;
#pragma unroll
            for (int n = 0; n < 4; n++) {
                int col = n0 + wn * 32 + n * 8 + qc * 2;
                float2 v;
                v.x = acc[t][n][half * 2 + 0];
                v.y = acc[t][n][half * 2 + 1];
                if (flags & 2) {
                    float2 b2 = *reinterpret_cast<const float2*>(bias + col);
                    v.x += b2.x; v.y += b2.y;
                }
                if (flags & 1) {
                    float2 o = *reinterpret_cast<const float2*>(crow + col);
                    v.x += o.x; v.y += o.y;
                }
                *reinterpret_cast<float2*>(crow + col) = v;
            }
        }
    }
#undef LOAD_STAGE
}

// ---------------- transpose + split: src[K,N] fp32 -> [N,K] bf16 hi/lo ------
__global__ void transpose_split_kernel(
    const float* __restrict__ src,
    __nv_bfloat16* __restrict__ dhi, __nv_bfloat16* __restrict__ dlo,
    int K, int N)
{
    __shared__ float tile[32][33];
    const int n0 = blockIdx.x * 32, k0 = blockIdx.y * 32;
    const int tx = threadIdx.x, ty = threadIdx.y;
#pragma unroll
    for (int i = 0; i < 32; i += 8)
        tile[ty + i][tx] = src[(size_t)(k0 + ty + i) * N + n0 + tx];
    __syncthreads();
#pragma unroll
    for (int i = 0; i < 32; i += 8) {
        float v = tile[tx][ty + i];
        __nv_bfloat16 h, l;
        split_bf(v, h, l);
        size_t idx = (size_t)(n0 + ty + i) * K + k0 + tx;
        dhi[idx] = h; dlo[idx] = l;
    }
}

__global__ void split_kernel(const float* __restrict__ src,
                             __nv_bfloat16* __restrict__ hi,
                             __nv_bfloat16* __restrict__ lo, size_t n)
{
    size_t idx = (size_t)blockIdx.x * blockDim.x + threadIdx.x;
    if (idx >= n) return;
    __nv_bfloat16 h, l;
    split_bf(src[idx], h, l);
    hi[idx] = h; lo[idx] = l;
}

__global__ void rope_table_kernel(float* __restrict__ cosb, float* __restrict__ sinb)
{
    int idx = blockIdx.x * blockDim.x + threadIdx.x;
    if (idx >= SEQ * 64) return;
    int s = idx >> 6, i = idx & 63;
    double inv = exp(-((double)(2 * i) / 128.0) * log(10000.0));
    double ang = (double)s * inv;
    cosb[idx] = (float)cos(ang);
    sinb[idx] = (float)sin(ang);
}

__global__ void embed_gather_kernel(const int* __restrict__ ids,
                                    const float* __restrict__ table,
                                    float* __restrict__ h)
{
    int idx = blockIdx.x * blockDim.x + threadIdx.x;
    if (idx >= B_ * SP * DLLM) return;
    int d = idx & (DLLM - 1);
    int r = (idx >> 12) & (SP - 1);
    int b = idx >> 19;
    int id = ids[b * SP + r];
    h[((size_t)(b * SEQ + r)) * DLLM + d] = table[(size_t)id * DLLM + d];
}

__global__ __launch_bounds__(256) void rmsnorm_kernel(
    const float* __restrict__ x, const float* __restrict__ w, float* __restrict__ out)
{
    int t = blockIdx.x;
    const float4* xr = reinterpret_cast<const float4*>(x + (size_t)t * DLLM);
    float4 vals[4];
    float s = 0.f;
#pragma unroll
    for (int j = 0; j < 4; j++) {
        float4 v = xr[threadIdx.x + j * 256];
        vals[j] = v;
        s += v.x * v.x + v.y * v.y + v.z * v.z + v.w * v.w;
    }
#pragma unroll
    for (int off = 16; off > 0; off >>= 1) s += __shfl_xor_sync(0xffffffffu, s, off);
    __shared__ float red[8];
    __shared__ float sscale;
    if ((threadIdx.x & 31) == 0) red[threadIdx.x >> 5] = s;
    __syncthreads();
    if (threadIdx.x == 0) {
        float r = 0.f;
#pragma unroll
        for (int i = 0; i < 8; i++) r += red[i];
        sscale = rsqrtf(r * (1.0f / DLLM) + EPS);
    }
    __syncthreads();
    float sc = sscale;
    const float4* w4 = reinterpret_cast<const float4*>(w);
    float4* o4 = reinterpret_cast<float4*>(out + (size_t)t * DLLM);
#pragma unroll
    for (int j = 0; j < 4; j++) {
        float4 v = vals[j];
        float4 wv = w4[threadIdx.x + j * 256];
        o4[threadIdx.x + j * 256] = make_float4(
            v.x * sc * wv.x, v.y * sc * wv.y, v.z * sc * wv.z, v.w * sc * wv.w);
    }
}

__global__ __launch_bounds__(256) void rmsnorm_split_kernel(
    const float* __restrict__ x, const float* __restrict__ w,
    __nv_bfloat16* __restrict__ ohi, __nv_bfloat16* __restrict__ olo)
{
    int t = blockIdx.x;
    const float4* xr = reinterpret_cast<const float4*>(x + (size_t)t * DLLM);
    float4 vals[4];
    float s = 0.f;
#pragma unroll
    for (int j = 0; j < 4; j++) {
        float4 v = xr[threadIdx.x + j * 256];
        vals[j] = v;
        s += v.x * v.x + v.y * v.y + v.z * v.z + v.w * v.w;
    }
#pragma unroll
    for (int off = 16; off > 0; off >>= 1) s += __shfl_xor_sync(0xffffffffu, s, off);
    __shared__ float red[8];
    __shared__ float sscale;
    if ((threadIdx.x & 31) == 0) red[threadIdx.x >> 5] = s;
    __syncthreads();
    if (threadIdx.x == 0) {
        float r = 0.f;
#pragma unroll
        for (int i = 0; i < 8; i++) r += red[i];
        sscale = rsqrtf(r * (1.0f / DLLM) + EPS);
    }
    __syncthreads();
    float sc = sscale;
    const float4* w4 = reinterpret_cast<const float4*>(w);
    size_t base = (size_t)t * DLLM;
#pragma unroll
    for (int j = 0; j < 4; j++) {
        float4 v = vals[j];
        float4 wv = w4[threadIdx.x + j * 256];
        float rr[4] = { v.x * sc * wv.x, v.y * sc * wv.y, v.z * sc * wv.z, v.w * sc * wv.w };
        size_t o = base + ((size_t)threadIdx.x + j * 256) * 4;
#pragma unroll
        for (int e = 0; e < 4; e++) {
            __nv_bfloat16 h, l;
            split_bf(rr[e], h, l);
            ohi[o + e] = h; olo[o + e] = l;
        }
    }
}

__global__ void rope_apply_kernel(float* __restrict__ qkv,
                                  const float* __restrict__ cosb,
                                  const float* __restrict__ sinb)
{
    int idx = blockIdx.x * blockDim.x + threadIdx.x;
    if (idx >= NTOK * NH * 64) return;
    int i = idx & 63;
    int h = (idx >> 6) & (NH - 1);
    int t = idx >> 11;
    int s = t & (SEQ - 1);
    float c = cosb[s * 64 + i];
    float sn = sinb[s * 64 + i];
    size_t base = (size_t)t * QKVS + h * HD + i;
    float x1 = qkv[base], x2 = qkv[base + 64];
    qkv[base]      = x1 * c - x2 * sn;
    qkv[base + 64] = x2 * c + x1 * sn;
    size_t kb = base + DLLM;
    x1 = qkv[kb]; x2 = qkv[kb + 64];
    qkv[kb]      = x1 * c - x2 * sn;
    qkv[kb + 64] = x2 * c + x1 * sn;
}

// Attention with fused bf16 hi/lo split epilogue
__global__ __launch_bounds__(256) void attention_kernel(
    const float* __restrict__ qkv,
    __nv_bfloat16* __restrict__ ohi, __nv_bfloat16* __restrict__ olo)
{
    __shared__ float sc[8][SEQ];
    const int b = blockIdx.z, hh = blockIdx.y;
    const int w = threadIdx.x >> 5, lane = threadIdx.x & 31;
    const int qi = blockIdx.x * 8 + w;
    const float scale = 0.088388347648318447f;

    const float* qrow = qkv + (size_t)(b * SEQ + qi) * QKVS + hh * HD;
    float4 qv = reinterpret_cast<const float4*>(qrow)[lane];

    const float* kbase = qkv + (size_t)b * SEQ * QKVS + DLLM + hh * HD;
    for (int kk = 0; kk <= qi; kk++) {
        float4 kv = reinterpret_cast<const float4*>(kbase + (size_t)kk * QKVS)[lane];
        float d = qv.x * kv.x + qv.y * kv.y + qv.z * kv.z + qv.w * kv.w;
#pragma unroll
        for (int off = 16; off > 0; off >>= 1) d += __shfl_xor_sync(0xffffffffu, d, off);
        if (lane == 0) sc[w][kk] = d * scale;
    }
    __syncwarp();

    float m = -1e30f;
    for (int kk = lane; kk <= qi; kk += 32) m = fmaxf(m, sc[w][kk]);
#pragma unroll
    for (int off = 16; off > 0; off >>= 1) m = fmaxf(m, __shfl_xor_sync(0xffffffffu, m, off));

    float ssum = 0.f;
    for (int kk = lane; kk <= qi; kk += 32) {
        float p = expf(sc[w][kk] - m);
        sc[w][kk] = p;
        ssum += p;
    }
#pragma unroll
    for (int off = 16; off > 0; off >>= 1) ssum += __shfl_xor_sync(0xffffffffu, ssum, off);
    __syncwarp();
    float inv = 1.0f / ssum;

    const float* vbase = qkv + (size_t)b * SEQ * QKVS + 2 * DLLM + hh * HD;
    float4 acc = make_float4(0.f, 0.f, 0.f, 0.f);
    for (int kk = 0; kk <= qi; kk++) {
        float p = sc[w][kk];
        float4 vv = reinterpret_cast<const float4*>(vbase + (size_t)kk * QKVS)[lane];
        acc.x += p * vv.x; acc.y += p * vv.y;
        acc.z += p * vv.z; acc.w += p * vv.w;
    }
    size_t o = (size_t)(b * SEQ + qi) * DLLM + hh * HD + lane * 4;
    float r[4] = { acc.x * inv, acc.y * inv, acc.z * inv, acc.w * inv };
#pragma unroll
    for (int e = 0; e < 4; e++) {
        __nv_bfloat16 h, l;
        split_bf(r[e], h, l);
        ohi[o + e] = h; olo[o + e] = l;
    }
}

__global__ void silu_mul_split_kernel(const float* __restrict__ gu,
                                      __nv_bfloat16* __restrict__ ohi,
                                      __nv_bfloat16* __restrict__ olo)
{
    int j = blockIdx.x * 256 + threadIdx.x;
    int t = blockIdx.y;
    const float* row = gu + (size_t)t * GUS;
    float x = row[j];
    float r = (x / (1.0f + expf(-x))) * row[DFF + j];
    __nv_bfloat16 h, l;
    split_bf(r, h, l);
    size_t o = (size_t)t * DFF + j;
    ohi[o] = h; olo[o] = l;
}

__global__ void pool_kernel(const float* __restrict__ xn, float* __restrict__ pooled)
{
    int idx = blockIdx.x * blockDim.x + threadIdx.x;
    if (idx >= B_ * DLLM) return;
    int b = idx >> 12, d = idx & (DLLM - 1);
    float s = 0.f;
    for (int t = 0; t < SEQ; t++)
        s += xn[(size_t)(b * SEQ + t) * DLLM + d];
    pooled[idx] = s * (1.0f / SEQ);
}

__global__ void head1_kernel(const float* __restrict__ pooled,
                             const float* __restrict__ W,
                             const float* __restrict__ bias,
                             float* __restrict__ y1)
{
    int b = blockIdx.x, j = threadIdx.x;
    const float* p = pooled + (size_t)b * DLLM;
    float s = bias[j];
    for (int i = 0; i < DLLM; i++) s += p[i] * W[(size_t)i * 768 + j];
    y1[b * 768 + j] = s;
}

__global__ void head2_kernel(const float* __restrict__ y1,
                             const float* __restrict__ W,
                             const float* __restrict__ bias,
                             float* __restrict__ out)
{
    int b = blockIdx.x;
    float s = 0.f;
    for (int j = threadIdx.x; j < 768; j += 256) s += y1[b * 768 + j] * W[j];
#pragma unroll
    for (int off = 16; off > 0; off >>= 1) s += __shfl_xor_sync(0xffffffffu, s, off);
    __shared__ float red[8];
    if ((threadIdx.x & 31) == 0) red[threadIdx.x >> 5] = s;
    __syncthreads();
    if (threadIdx.x == 0) {
        float r = 0.f;
#pragma unroll
        for (int i = 0; i < 8; i++) r += red[i];
        out[b] = r + bias[0];
    }
}

// ---------------------------------------------------------------------------
extern "C" void kernel_launch(void* const* d_in, const int* in_sizes, int n_in,
                              void* d_out, int out_size)
{
    const float* text  = (const float*)d_in[0];
    const float* vis   = (const float*)d_in[1];
    const int*   ids   = (const int*)  d_in[2];
    const float* inW   = (const float*)d_in[3];
    const float* inb   = (const float*)d_in[4];
    const float* etab  = (const float*)d_in[5];
    const float* Wq    = (const float*)d_in[6];
    const float* Wk    = (const float*)d_in[7];
    const float* Wv    = (const float*)d_in[8];
    const float* Wo    = (const float*)d_in[9];
    const float* ln1   = (const float*)d_in[10];
    const float* ln2   = (const float*)d_in[11];
    const float* Wg    = (const float*)d_in[12];
    const float* Wu    = (const float*)d_in[13];
    const float* Wd    = (const float*)d_in[14];
    const float* fnw   = (const float*)d_in[15];
    const float* o1W   = (const float*)d_in[16];
    const float* o1b   = (const float*)d_in[17];
    const float* o2W   = (const float*)d_in[18];
    const float* o2b   = (const float*)d_in[19];
    float* out = (float*)d_out;

    cudaFuncSetAttribute(gemm_tc, cudaFuncAttributeMaxDynamicSharedMemorySize,
                         GSMEM_BYTES);

    float* S = nullptr;
    cudaGetSymbolAddress((void**)&S, g_scratch);
    __nv_bfloat16* BS = nullptr;
    cudaGetSymbolAddress((void**)&BS, g_bf);

    float* h    = S + OFF_H;
    float* xn   = S + OFF_XN;
    float* qkv  = S + OFF_QKV;
    float* gu   = S + OFF_GU;
    float* cosb = S + OFF_COS;
    float* sinb = S + OFF_SIN;
    float* pooled = S + OFF_POOL;
    float* y1   = S + OFF_Y1;

    __nv_bfloat16 *xnh = BS + BO_XNH, *xnl = BS + BO_XNL;
    __nv_bfloat16 *ath = BS + BO_ATH, *atl = BS + BO_ATL;
    __nv_bfloat16 *gh  = BS + BO_GH,  *gl  = BS + BO_GL;
    __nv_bfloat16 *txh = BS + BO_TXH, *txl = BS + BO_TXL;
    __nv_bfloat16 *vxh = BS + BO_VXH, *vxl = BS + BO_VXL;
    __nv_bfloat16 *inwh = BS + BO_INWH, *inwl = BS + BO_INWL;

    dim3 t32(32, 8);

    rope_table_kernel<<<(SEQ * 64 + 255) / 256, 256>>>(cosb, sinb);

    transpose_split_kernel<<<dim3(DLLM / 32, DMODEL / 32), t32>>>(inW, inwh, inwl, DMODEL, DLLM);
    for (int l = 0; l < 2; l++) {
        transpose_split_kernel<<<dim3(DLLM / 32, DLLM / 32), t32>>>(
            Wq + (size_t)l * W4, BS + BO_QKVH + (size_t)l * 3 * W4,
            BS + BO_QKVL + (size_t)l * 3 * W4, DLLM, DLLM);
        transpose_split_kernel<<<dim3(DLLM / 32, DLLM / 32), t32>>>(
            Wk + (size_t)l * W4, BS + BO_QKVH + (size_t)l * 3 * W4 + W4,
            BS + BO_QKVL + (size_t)l * 3 * W4 + W4, DLLM, DLLM);
        transpose_split_kernel<<<dim3(DLLM / 32, DLLM / 32), t32>>>(
            Wv + (size_t)l * W4, BS + BO_QKVH + (size_t)l * 3 * W4 + 2 * W4,
            BS + BO_QKVL + (size_t)l * 3 * W4 + 2 * W4, DLLM, DLLM);
        transpose_split_kernel<<<dim3(DLLM / 32, DLLM / 32), t32>>>(
            Wo + (size_t)l * W4, BS + BO_OH + (size_t)l * W4,
            BS + BO_OL + (size_t)l * W4, DLLM, DLLM);
        transpose_split_kernel<<<dim3(DFF / 32, DLLM / 32), t32>>>(
            Wg + (size_t)l * WF, BS + BO_GUH + (size_t)l * 2 * WF,
            BS + BO_GUL + (size_t)l * 2 * WF, DLLM, DFF);
        transpose_split_kernel<<<dim3(DFF / 32, DLLM / 32), t32>>>(
            Wu + (size_t)l * WF, BS + BO_GUH + (size_t)l * 2 * WF + WF,
            BS + BO_GUL + (size_t)l * 2 * WF + WF, DLLM, DFF);
        transpose_split_kernel<<<dim3(DLLM / 32, DFF / 32), t32>>>(
            Wd + (size_t)l * WF, BS + BO_DWH + (size_t)l * WF,
            BS + BO_DWL + (size_t)l * WF, DFF, DLLM);
    }

    embed_gather_kernel<<<(B_ * SP * DLLM + 255) / 256, 256>>>(ids, etab, h);
    split_kernel<<<(int)((SZ_TV + 255) / 256), 256>>>(text, txh, txl, SZ_TV);
    split_kernel<<<(int)((SZ_TV + 255) / 256), 256>>>(vis, vxh, vxl, SZ_TV);
    gemm_tc<<<dim3(DLLM / 64, 512 / 128), 256, GSMEM_BYTES>>>(
        txh, txl, inwh, inwl, h, 512, DLLM, DMODEL, 2 | 4, inb, SP);
    gemm_tc<<<dim3(DLLM / 64, 512 / 128), 256, GSMEM_BYTES>>>(
        vxh, vxl, inwh, inwl, h, 512, DLLM, DMODEL, 2 | 4, inb, SP + ST);

    for (int l = 0; l < 2; l++) {
        rmsnorm_split_kernel<<<NTOK, 256>>>(h, ln1 + (size_t)l * DLLM, xnh, xnl);
        gemm_tc<<<dim3(QKVS / 64, NTOK / 128), 256, GSMEM_BYTES>>>(
            xnh, xnl, BS + BO_QKVH + (size_t)l * 3 * W4, BS + BO_QKVL + (size_t)l * 3 * W4,
            qkv, NTOK, QKVS, DLLM, 0, nullptr, 0);
        rope_apply_kernel<<<(NTOK * NH * 64 + 255) / 256, 256>>>(qkv, cosb, sinb);
        attention_kernel<<<dim3(SEQ / 8, NH, B_), 256>>>(qkv, ath, atl);
        gemm_tc<<<dim3(DLLM / 64, NTOK / 128), 256, GSMEM_BYTES>>>(
            ath, atl, BS + BO_OH + (size_t)l * W4, BS + BO_OL + (size_t)l * W4,
            h, NTOK, DLLM, DLLM, 1, nullptr, 0);

        rmsnorm_split_kernel<<<NTOK, 256>>>(h, ln2 + (size_t)l * DLLM, xnh, xnl);
        gemm_tc<<<dim3(GUS / 64, NTOK / 128), 256, GSMEM_BYTES>>>(
            xnh, xnl, BS + BO_GUH + (size_t)l * 2 * WF, BS + BO_GUL + (size_t)l * 2 * WF,
            gu, NTOK, GUS, DLLM, 0, nullptr, 0);
        silu_mul_split_kernel<<<dim3(DFF / 256, NTOK), 256>>>(gu, gh, gl);
        gemm_tc<<<dim3(DLLM / 64, NTOK / 128), 256, GSMEM_BYTES>>>(
            gh, gl, BS + BO_DWH + (size_t)l * WF, BS + BO_DWL + (size_t)l * WF,
            h, NTOK, DLLM, DFF, 1, nullptr, 0);
    }

    rmsnorm_kernel<<<NTOK, 256>>>(h, fnw, xn);
    pool_kernel<<<(B_ * DLLM + 255) / 256, 256>>>(xn, pooled);
    head1_kernel<<<B_, 768>>>(pooled, o1W, o1b, y1);
    head2_kernel<<<B_, 256>>>(y1, o2W, o2b, out);
}